// round 14
// baseline (speedup 1.0000x reference)
#include <cuda_runtime.h>
#include <cstdint>

#define DEVFN __device__ __forceinline__

// ---------------------------------------------------------------------------
// Scratch (static device globals — no allocations anywhere)
// Quantized activations stored HALO-PADDED: (IDp=ID+2, IHp=IH+2, IWp=IW+2
// rounded even), left-pad 1, halo = 0 (conv zero-padding materialized).
// ---------------------------------------------------------------------------
__device__ float          g_h1 [33554432u];            // conv1 out fp32
__device__ unsigned short g_h1q[42614784u];            // 32*64*18*34*34
__device__ float          g_c2 [8388608u];
__device__ float          g_c2p[2u * 8388608u];        // conv2 split-K partials
__device__ unsigned short g_c2q[13271040u];            // 32*128*10*18*18
__device__ float          g_c3 [2097152u];
__device__ float          g_c3p[2u * 2097152u];
__device__ unsigned short g_c3q[4915200u];             // 32*256*6*10*10
__device__ float          g_c4 [524288u];
__device__ float          g_c4p[8u * 524288u];
__device__ signed char    g_w2h[524288u],  g_w2l[524288u];
__device__ signed char    g_w3h[2097152u], g_w3l[2097152u];
__device__ signed char    g_w4h[8388608u], g_w4l[8388608u];
__device__ int            g_amax[8];                   // float bits, >= 0
__device__ float          g_bnscale[512];
__device__ float          g_bnshift[512];
__device__ float          g_d[32 * 32];

#define QMAX 32512.0f

// ---------------------------------------------------------------------------
// Helpers
// ---------------------------------------------------------------------------
DEVFN uint32_t smem_u32(const void* p)
{
    uint32_t a;
    asm("{ .reg .u64 t; cvta.to.shared.u64 t, %1; cvt.u32.u64 %0, t; }"
        : "=r"(a) : "l"(p));
    return a;
}

DEVFN void ldsm4(uint32_t* r, uint32_t addr)
{
    asm volatile("ldmatrix.sync.aligned.m8n8.x4.shared.b16 {%0,%1,%2,%3}, [%4];"
                 : "=r"(r[0]), "=r"(r[1]), "=r"(r[2]), "=r"(r[3]) : "r"(addr));
}

DEVFN void imma(int* c, const uint32_t* a, uint32_t b0, uint32_t b1)
{
    asm volatile(
        "mma.sync.aligned.m16n8k32.row.col.s32.s8.s8.s32 "
        "{%0,%1,%2,%3}, {%4,%5,%6,%7}, {%8,%9}, {%0,%1,%2,%3};"
        : "+r"(c[0]), "+r"(c[1]), "+r"(c[2]), "+r"(c[3])
        : "r"(a[0]), "r"(a[1]), "r"(a[2]), "r"(a[3]), "r"(b0), "r"(b1));
}

DEVFN void cpa16(uint32_t dst, const void* src)
{
    asm volatile("cp.async.cg.shared.global [%0], [%1], 16;"
                 :: "r"(dst), "l"(src) : "memory");
}
#define CP_COMMIT() asm volatile("cp.async.commit_group;" ::: "memory")

DEVFN void amax_atomic(int idx, float v)
{
    atomicMax(&g_amax[idx], __float_as_int(v));
}

DEVFN unsigned short quant16(float v, float inv)
{
    float q = rintf(v * inv);
    q = fminf(fmaxf(q, -QMAX), QMAX);
    const int Q = (int)q;
    const int h = (Q + 128) >> 8;          // h in [-127,127]
    const int l = Q - (h << 8);            // l in [-128,127]
    return (unsigned short)(((h & 0xff) << 8) | (l & 0xff));
}

// ---------------------------------------------------------------------------
// Setup kernels (fused across the 3 weight tensors)
// ---------------------------------------------------------------------------
__global__ void zeroamax_kernel()
{
    if (threadIdx.x < 8) g_amax[threadIdx.x] = 0;
}

__global__ void wamax3_kernel(const float4* __restrict__ w2,
                              const float4* __restrict__ w3,
                              const float4* __restrict__ w4)
{
    const int which = blockIdx.y;
    const float4* w = (which == 0) ? w2 : (which == 1) ? w3 : w4;
    const int n4    = (which == 0) ? 131072 : (which == 1) ? 524288 : 2097152;
    const int idx   = (which == 0) ? 1 : (which == 1) ? 3 : 5;

    const int stride = gridDim.x * 256;
    float am = 0.f;
    for (int i = blockIdx.x * 256 + threadIdx.x; i < n4; i += stride) {
        const float4 v = w[i];
        am = fmaxf(am, fmaxf(fmaxf(fabsf(v.x), fabsf(v.y)),
                             fmaxf(fabsf(v.z), fabsf(v.w))));
    }
    __shared__ float sh[256];
    sh[threadIdx.x] = am;
    __syncthreads();
    for (int o = 128; o > 0; o >>= 1) {
        if (threadIdx.x < o) sh[threadIdx.x] = fmaxf(sh[threadIdx.x], sh[threadIdx.x + o]);
        __syncthreads();
    }
    if (threadIdx.x == 0) amax_atomic(idx, sh[0]);
}

__global__ void wquant3_kernel(const float* __restrict__ w2,
                               const float* __restrict__ w3,
                               const float* __restrict__ w4,
                               signed char* __restrict__ o2h, signed char* __restrict__ o2l,
                               signed char* __restrict__ o3h, signed char* __restrict__ o3l,
                               signed char* __restrict__ o4h, signed char* __restrict__ o4l)
{
    const int which = blockIdx.y;
    const float* w = (which == 0) ? w2 : (which == 1) ? w3 : w4;
    signed char* oh = (which == 0) ? o2h : (which == 1) ? o3h : o4h;
    signed char* ol = (which == 0) ? o2l : (which == 1) ? o3l : o4l;
    const int n   = (which == 0) ? 524288 : (which == 1) ? 2097152 : 8388608;
    const int idx = (which == 0) ? 1 : (which == 1) ? 3 : 5;

    const float amax = __int_as_float(g_amax[idx]);
    const float inv = QMAX / fmaxf(amax, 1e-30f);
    const int stride = gridDim.x * 256;
    for (int i = blockIdx.x * 256 + threadIdx.x; i < n; i += stride) {
        const unsigned short q = quant16(w[i], inv);
        oh[i] = (signed char)(q >> 8);
        ol[i] = (signed char)(q & 0xff);
    }
}

// ---------------------------------------------------------------------------
// Padded quantizers, FLAT-indexed (thread -> one u32 = 2 elements).
// ---------------------------------------------------------------------------
__global__ void quantA_pad_kernel(const float* __restrict__ in,
                                  unsigned* __restrict__ out,
                                  int ID, int IH, int IW,
                                  int IDp, int IHp, int IWp2, int amaxIdx)
{
    const int hw = blockIdx.x * 256 + threadIdx.x;
    const int HW = IHp * IWp2;
    if (hw >= HW) return;
    const int hp = hw / IWp2;
    const int w2 = hw - hp * IWp2;
    const int dp = blockIdx.y;
    const int z  = blockIdx.z;

    const float amax = __int_as_float(g_amax[amaxIdx]);
    const float inv = QMAX / fmaxf(amax, 1e-30f);

    float v0 = 0.f, v1 = 0.f;
    if (dp >= 1 && dp <= ID && hp >= 1 && hp <= IH) {
        const size_t srcrow = (((size_t)z * ID + (dp - 1)) * IH + (hp - 1)) * IW;
        const int wp0 = 2 * w2;
        if (wp0 >= 1 && wp0 <= IW) v0 = in[srcrow + wp0 - 1];
        if (wp0 + 1 <= IW)         v1 = in[srcrow + wp0];
    }
    out[((size_t)z * IDp + dp) * HW + hw] =
        (unsigned)quant16(v0, inv) | ((unsigned)quant16(v1, inv) << 16);
}

__global__ void quantBN_pad_kernel(const float* __restrict__ in,
                                   unsigned* __restrict__ out,
                                   int Cmask, int ID, int IH, int IW,
                                   int IDp, int IHp, int IWp2, int amaxIdx)
{
    const int hw = blockIdx.x * 256 + threadIdx.x;
    const int HW = IHp * IWp2;
    if (hw >= HW) return;
    const int hp = hw / IWp2;
    const int w2 = hw - hp * IWp2;
    const int dp = blockIdx.y;
    const int z  = blockIdx.z;
    const int c  = z & Cmask;

    const float sc = g_bnscale[c], sh = g_bnshift[c];
    const float amax = __int_as_float(g_amax[amaxIdx]);
    const float inv = QMAX / fmaxf(amax, 1e-30f);

    float v0 = 0.f, v1 = 0.f;
    if (dp >= 1 && dp <= ID && hp >= 1 && hp <= IH) {
        const size_t srcrow = (((size_t)z * ID + (dp - 1)) * IH + (hp - 1)) * IW;
        const int wp0 = 2 * w2;
        if (wp0 >= 1 && wp0 <= IW) {
            float v = in[srcrow + wp0 - 1] * sc + sh;
            v0 = (v >= 0.f) ? v : 0.2f * v;
        }
        if (wp0 + 1 <= IW) {
            float v = in[srcrow + wp0] * sc + sh;
            v1 = (v >= 0.f) ? v : 0.2f * v;
        }
    }
    out[((size_t)z * IDp + dp) * HW + hw] =
        (unsigned)quant16(v0, inv) | ((unsigned)quant16(v1, inv) << 16);
}

// ---------------------------------------------------------------------------
// Layer 1: conv3d (64,1,2,4,4), stride (2,2,2), pad (0,1,1), fused lrelu.
// Input slab staged in smem with halo.
// ---------------------------------------------------------------------------
#define XPLN (66 * 68)

__global__ __launch_bounds__(1024, 1)
void conv1_kernel(const float* __restrict__ x, const float* __restrict__ w1)
{
    __shared__ float ws[2048];
    __shared__ float xs[2 * XPLN];
    __shared__ float sm[1024];

    const int t = threadIdx.x;
    for (int i = t; i < 2048; i += 1024) ws[i] = w1[i];
    for (int i = t; i < 2 * XPLN; i += 1024) xs[i] = 0.f;
    __syncthreads();

    const int od = blockIdx.x;
    const int n  = blockIdx.y;
    const float* xb = x + (size_t)n * 131072 + (size_t)(od * 2) * 4096;

    for (int i = t; i < 8192; i += 1024) {
        const int kd = i >> 12;
        const int r  = (i >> 6) & 63;
        const int c  = i & 63;
        xs[kd * XPLN + (r + 1) * 68 + (c + 1)] = xb[kd * 4096 + r * 64 + c];
    }
    __syncthreads();

    const int oh = t >> 5;
    const int ow = t & 31;

    float v[32];
#pragma unroll
    for (int kd = 0; kd < 2; ++kd)
#pragma unroll
        for (int kh = 0; kh < 4; ++kh)
#pragma unroll
            for (int kw = 0; kw < 4; ++kw)
                v[kd * 16 + kh * 4 + kw] =
                    xs[kd * XPLN + (oh * 2 + kh) * 68 + (ow * 2 + kw)];

    float* outb = g_h1 + ((size_t)(n * 64) * 16 + od) * 1024 + t;
    float am = 0.f;
#pragma unroll 4
    for (int c = 0; c < 64; ++c) {
        const float4* wp = (const float4*)&ws[c * 32];
        float acc = 0.f;
#pragma unroll
        for (int q = 0; q < 8; ++q) {
            const float4 w4 = wp[q];
            acc += v[q * 4 + 0] * w4.x + v[q * 4 + 1] * w4.y
                 + v[q * 4 + 2] * w4.z + v[q * 4 + 3] * w4.w;
        }
        acc = (acc >= 0.f) ? acc : 0.2f * acc;
        am = fmaxf(am, fabsf(acc));
        outb[(size_t)c * 16384] = acc;
    }

    sm[t] = am;
    __syncthreads();
    for (int o = 512; o > 0; o >>= 1) {
        if (t < o) sm[t] = fmaxf(sm[t], sm[t + o]);
        __syncthreads();
    }
    if (t == 0) amax_atomic(0, sm[0]);
}

// ---------------------------------------------------------------------------
// int8 IMMA implicit-GEMM conv3d, HALO-PADDED input, K-CHUNK 64.
// CTA 128x128, 16 warps (4x4), warp tile 32x32. 3-stage pipeline.
// ---------------------------------------------------------------------------
#define ROWB 80
#define TILE (128 * ROWB)
#define BUF  (4 * TILE)
#define CI_SMEM (3 * BUF)     // 122880 B

__global__ __launch_bounds__(512, 1)
void convimma_kernel(const unsigned short* __restrict__ inq,
                     const signed char* __restrict__ wh,
                     const signed char* __restrict__ wl,
                     float* __restrict__ out,
                     int Cin, int Cout, int OD, int OH, int OW,
                     int IDp, int IHp, int IWp,
                     int kPerSplit, int sliceElems, int iaIdx, int ibIdx)
{
    extern __shared__ unsigned char dsm[];
    const uint32_t smb = smem_u32(dsm);

    const int t    = threadIdx.x;
    const int lane = t & 31;
    const int wid  = t >> 5;
    const int mw   = (wid & 3) * 32;
    const int nww  = (wid >> 2) * 32;

    const int OHW  = OH * OW;
    const int ODHW = OD * OHW;
    const int IHWp = IHp * IWp;
    const int IWp2 = IWp >> 1;
    const int K    = Cin * 64;

    const int mBase = blockIdx.x * 128;
    const int cBase = blockIdx.y * 128;
    const int kBase = blockIdx.z * kPerSplit;

    const int lm = t >> 2;
    const int kq = t & 3;
    const int mload = mBase + lm;
    const int n_l = mload / ODHW;
    int srem = mload % ODHW;
    const int od = srem / OHW; srem %= OHW;
    const int oh = srem / OW;
    const int ow = srem % OW;

    const int rowElem0 = (oh * 2) * IWp + 2 * ow;
    const uint32_t aOff = (uint32_t)(lm * ROWB + kq * 16);

    const int brow = t & 127;
    const int bpl  = (t >> 7) & 1;
    const int bh2  = (t >> 8) & 1;
    const signed char* wsrc = (bpl ? wl : wh) + (size_t)(cBase + brow) * K
                            + kBase + bh2 * 32;
    const uint32_t bDst = (uint32_t)((2 + bpl) * TILE + brow * ROWB + bh2 * 32);

    const uint32_t lrow = (lane & 15);
    const uint32_t lsel = (lane >> 4) * 16;

    int acc_hh[2][4][4], acc_md[2][4][4];
#pragma unroll
    for (int a = 0; a < 2; ++a)
#pragma unroll
        for (int b = 0; b < 4; ++b)
#pragma unroll
            for (int q = 0; q < 4; ++q) { acc_hh[a][b][q] = 0; acc_md[a][b][q] = 0; }

    const int nCh = kPerSplit >> 6;

    unsigned wA[8];
    auto gatherA = [&](int kc) {
        const int cin = (kBase >> 6) + kc;
        const int idp = od * 2 + kq;
        const unsigned* p = (const unsigned*)(inq
            + ((size_t)(n_l * Cin + cin) * IDp + idp) * IHWp + rowElem0);
#pragma unroll
        for (int kh = 0; kh < 4; ++kh) {
            wA[2 * kh]     = p[kh * IWp2];
            wA[2 * kh + 1] = p[kh * IWp2 + 1];
        }
    };

    auto cpasyncB = [&](int kc, int buf) {
        const uint32_t d = smb + buf * BUF + bDst;
        const signed char* s = wsrc + ((size_t)kc << 6);
        cpa16(d, s);
        cpa16(d + 16, s + 16);
        CP_COMMIT();
    };

    auto storeA = [&](int buf) {
        unsigned char* base = dsm + buf * BUF + aOff;
        uint4 hi, lo;
        hi.x = __byte_perm(wA[0], wA[1], 0x7531);
        lo.x = __byte_perm(wA[0], wA[1], 0x6420);
        hi.y = __byte_perm(wA[2], wA[3], 0x7531);
        lo.y = __byte_perm(wA[2], wA[3], 0x6420);
        hi.z = __byte_perm(wA[4], wA[5], 0x7531);
        lo.z = __byte_perm(wA[4], wA[5], 0x6420);
        hi.w = __byte_perm(wA[6], wA[7], 0x7531);
        lo.w = __byte_perm(wA[6], wA[7], 0x6420);
        *(uint4*)(base)        = hi;
        *(uint4*)(base + TILE) = lo;
    };

    gatherA(0);
    cpasyncB(0, 0);
    storeA(0);
    gatherA(1);
    cpasyncB(1, 1);
    storeA(1);

    for (int kc = 0; kc < nCh; ++kc) {
        const int pf = kc + 2;

        if (kc + 1 < nCh)
            asm volatile("cp.async.wait_group 1;" ::: "memory");
        else
            asm volatile("cp.async.wait_group 0;" ::: "memory");
        __syncthreads();

        if (pf < nCh) { cpasyncB(pf, pf % 3); gatherA(pf); }

        const uint32_t aH = smb + (kc % 3) * BUF;
        const uint32_t aL = aH + TILE;
        const uint32_t bH = aH + 2 * TILE;
        const uint32_t bL = aH + 3 * TILE;

#pragma unroll
        for (int ks = 0; ks < 2; ++ks) {
            const uint32_t sel = lsel + ks * 32;
            uint32_t ah[2][4], al[2][4], bh[2][4], bl[2][4];
#pragma unroll
            for (int tm = 0; tm < 2; ++tm) {
                const uint32_t ro = (uint32_t)(mw + tm * 16 + lrow) * ROWB + sel;
                ldsm4(ah[tm], aH + ro);
                ldsm4(al[tm], aL + ro);
            }
#pragma unroll
            for (int bt = 0; bt < 2; ++bt) {
                const uint32_t ro = (uint32_t)(nww + bt * 16 + lrow) * ROWB + sel;
                ldsm4(bh[bt], bH + ro);
                ldsm4(bl[bt], bL + ro);
            }
#pragma unroll
            for (int tm = 0; tm < 2; ++tm)
#pragma unroll
                for (int bt = 0; bt < 2; ++bt)
#pragma unroll
                    for (int sub = 0; sub < 2; ++sub) {
                        const int tn = bt * 2 + sub;
                        imma(acc_hh[tm][tn], ah[tm], bh[bt][sub], bh[bt][sub + 2]);
                        imma(acc_md[tm][tn], ah[tm], bl[bt][sub], bl[bt][sub + 2]);
                        imma(acc_md[tm][tn], al[tm], bh[bt][sub], bh[bt][sub + 2]);
                    }
        }

        if (pf < nCh) storeA(pf % 3);
    }

    // ---- epilogue ----
    const float amA = __int_as_float(g_amax[iaIdx]);
    const float amB = __int_as_float(g_amax[ibIdx]);
    const float sAB = (amA / QMAX) * (amB / QMAX);

    float* outz = out + (size_t)blockIdx.z * sliceElems;
#pragma unroll
    for (int tm = 0; tm < 2; ++tm) {
#pragma unroll
        for (int half = 0; half < 2; ++half) {
            const int m   = mBase + mw + tm * 16 + (lane >> 2) + 8 * half;
            const int n_o = m / ODHW;
            const int s_o = m % ODHW;
            float* ob = outz + (size_t)(n_o * Cout + cBase) * ODHW + s_o;
#pragma unroll
            for (int tn = 0; tn < 4; ++tn) {
                const int col = nww + tn * 8 + 2 * (lane & 3);
                const float v0 = sAB * fmaf(65536.f,
                    (float)acc_hh[tm][tn][half * 2 + 0],
                    256.f * (float)acc_md[tm][tn][half * 2 + 0]);
                const float v1 = sAB * fmaf(65536.f,
                    (float)acc_hh[tm][tn][half * 2 + 1],
                    256.f * (float)acc_md[tm][tn][half * 2 + 1]);
                ob[(size_t)col * ODHW]       = v0;
                ob[(size_t)(col + 1) * ODHW] = v1;
            }
        }
    }
}

// ---------------------------------------------------------------------------
// Fused split-K reduction + BatchNorm stats (+ activated amax from extremes).
// One block per channel: sums nSlices partials per element, writes the
// reduced tensor, and accumulates mean/var/min/max in the same pass.
// ---------------------------------------------------------------------------
__global__ void bnstats_red_kernel(const float* __restrict__ partials,
                                   float* __restrict__ outbuf,
                                   const float* __restrict__ g,
                                   const float* __restrict__ b,
                                   int C, int ODHW, int nSlices, int sliceElems,
                                   int amaxIdx)
{
    const int c = blockIdx.x;
    const int t = threadIdx.x;
    double s = 0.0, s2 = 0.0;
    float mn = 3.0e38f, mx = -3.0e38f;
    for (int n = 0; n < 32; ++n) {
        const size_t base = ((size_t)n * C + c) * ODHW;
        for (int sp = t; sp < ODHW; sp += 256) {
            const size_t off = base + sp;
            float f = partials[off];
            for (int z = 1; z < nSlices; ++z)
                f += partials[off + (size_t)z * sliceElems];
            outbuf[off] = f;
            const double v = (double)f;
            s += v; s2 += v * v;
            mn = fminf(mn, f); mx = fmaxf(mx, f);
        }
    }
    __shared__ double sh[256], sh2[256];
    __shared__ float smn[256], smx[256];
    sh[t] = s; sh2[t] = s2; smn[t] = mn; smx[t] = mx;
    __syncthreads();
    for (int o = 128; o > 0; o >>= 1) {
        if (t < o) {
            sh[t] += sh[t + o]; sh2[t] += sh2[t + o];
            smn[t] = fminf(smn[t], smn[t + o]);
            smx[t] = fmaxf(smx[t], smx[t + o]);
        }
        __syncthreads();
    }
    if (t == 0) {
        const double cnt  = 32.0 * (double)ODHW;
        const double mean = sh[0] / cnt;
        const double var  = sh2[0] / cnt - mean * mean;
        const double scd  = (double)g[c] / sqrt(var + 1e-5);
        const float sc = (float)scd;
        const float shv = (float)((double)b[c] - mean * scd);
        g_bnscale[c] = sc;
        g_bnshift[c] = shv;
        if (amaxIdx >= 0) {
            float a1 = smx[0] * sc + shv; a1 = (a1 >= 0.f) ? a1 : 0.2f * a1;
            float a2 = smn[0] * sc + shv; a2 = (a2 >= 0.f) ? a2 : 0.2f * a2;
            amax_atomic(amaxIdx, fmaxf(fabsf(a1), fabsf(a2)));
        }
    }
}

// ---------------------------------------------------------------------------
// BN apply + lrelu in place (fp32, conv4 output).
// ---------------------------------------------------------------------------
__global__ void bn_lrelu_kernel(float4* __restrict__ x, int C, int ODHW4, int total4)
{
    const int i = blockIdx.x * 256 + threadIdx.x;
    if (i >= total4) return;
    const int c = (i / ODHW4) % C;
    const float sc = g_bnscale[c], sh = g_bnshift[c];
    float4 v = x[i];
    v.x = v.x * sc + sh; v.x = (v.x >= 0.f) ? v.x : 0.2f * v.x;
    v.y = v.y * sc + sh; v.y = (v.y >= 0.f) ? v.y : 0.2f * v.y;
    v.z = v.z * sc + sh; v.z = (v.z >= 0.f) ? v.z : 0.2f * v.z;
    v.w = v.w * sc + sh; v.w = (v.w >= 0.f) ? v.w : 0.2f * v.w;
    x[i] = v;
}

// ---------------------------------------------------------------------------
// Minibatch discrimination + final reduction.
// ---------------------------------------------------------------------------
__global__ void pairwise_kernel()
{
    const int i = blockIdx.y, j = blockIdx.x, t = threadIdx.x;
    const float* a = g_c4 + (size_t)i * 16384;
    const float* b = g_c4 + (size_t)j * 16384;
    float s = 0.f;
    for (int k = t; k < 16384; k += 256) s += fabsf(a[k] - b[k]);
    __shared__ float sh[256];
    sh[t] = s;
    __syncthreads();
    for (int o = 128; o > 0; o >>= 1) {
        if (t < o) sh[t] += sh[t + o];
        __syncthreads();
    }
    if (t == 0)
        g_d[i * 32 + j] = sh[0] * (1.f / 16384.f) + ((i == j) ? 1e6f : 0.f);
}

__global__ void final_kernel(const float* __restrict__ w5, float* __restrict__ out)
{
    const int n = blockIdx.x, t = threadIdx.x;

    __shared__ float shm[256];
    shm[t] = (t < 32) ? g_d[n * 32 + t] : 1e30f;
    __syncthreads();
    for (int o = 128; o > 0; o >>= 1) {
        if (t < o) shm[t] = fminf(shm[t], shm[t + o]);
        __syncthreads();
    }
    const float s = shm[0];
    __syncthreads();

    double acc = 0.0;
    const float* h = g_c4 + (size_t)n * 16384;
    for (int k = t; k < 16384; k += 256)
        acc += (double)h[k] * (double)w5[k];
    if (t < 32)
        acc += (double)s * (double)w5[16384 + t];

    __shared__ double shd[256];
    shd[t] = acc;
    __syncthreads();
    for (int o = 128; o > 0; o >>= 1) {
        if (t < o) shd[t] += shd[t + o];
        __syncthreads();
    }
    if (t == 0) out[n] = (float)shd[0];
}

// ---------------------------------------------------------------------------
// Launch chain. Inputs: x, w1, w2, g2, b2, w3, g3, b3, w4, g4, b4, w5
// ---------------------------------------------------------------------------
extern "C" void kernel_launch(void* const* d_in, const int* in_sizes, int n_in,
                              void* d_out, int out_size)
{
    (void)in_sizes; (void)n_in; (void)out_size;
    const float* x  = (const float*)d_in[0];
    const float* w1 = (const float*)d_in[1];
    const float* w2 = (const float*)d_in[2];
    const float* g2 = (const float*)d_in[3];
    const float* b2 = (const float*)d_in[4];
    const float* w3 = (const float*)d_in[5];
    const float* g3 = (const float*)d_in[6];
    const float* b3 = (const float*)d_in[7];
    const float* w4 = (const float*)d_in[8];
    const float* g4 = (const float*)d_in[9];
    const float* b4 = (const float*)d_in[10];
    const float* w5 = (const float*)d_in[11];
    float* out = (float*)d_out;

    float *h1, *c2, *c2p, *c3, *c3p, *c4, *c4p;
    unsigned short *h1q, *c2q, *c3q;
    signed char *w2h, *w2l, *w3h, *w3l, *w4h, *w4l;
    cudaGetSymbolAddress((void**)&h1,  g_h1);
    cudaGetSymbolAddress((void**)&h1q, g_h1q);
    cudaGetSymbolAddress((void**)&c2,  g_c2);
    cudaGetSymbolAddress((void**)&c2p, g_c2p);
    cudaGetSymbolAddress((void**)&c2q, g_c2q);
    cudaGetSymbolAddress((void**)&c3,  g_c3);
    cudaGetSymbolAddress((void**)&c3p, g_c3p);
    cudaGetSymbolAddress((void**)&c3q, g_c3q);
    cudaGetSymbolAddress((void**)&c4,  g_c4);
    cudaGetSymbolAddress((void**)&c4p, g_c4p);
    cudaGetSymbolAddress((void**)&w2h, g_w2h);
    cudaGetSymbolAddress((void**)&w2l, g_w2l);
    cudaGetSymbolAddress((void**)&w3h, g_w3h);
    cudaGetSymbolAddress((void**)&w3l, g_w3l);
    cudaGetSymbolAddress((void**)&w4h, g_w4h);
    cudaGetSymbolAddress((void**)&w4l, g_w4l);

    cudaFuncSetAttribute(convimma_kernel,
                         cudaFuncAttributeMaxDynamicSharedMemorySize, CI_SMEM);

    // amax init + fused weight amax/quant
    zeroamax_kernel<<<1, 32>>>();
    wamax3_kernel<<<dim3(256, 3), 256>>>((const float4*)w2, (const float4*)w3,
                                         (const float4*)w4);
    wquant3_kernel<<<dim3(4096, 3), 256>>>(w2, w3, w4,
                                           w2h, w2l, w3h, w3l, w4h, w4l);

    // L1 + padded quantize (h1: 16,32,32 -> 18,34,34; IWp2=17)
    conv1_kernel<<<dim3(16, 32), 1024>>>(x, w1);
    quantA_pad_kernel<<<dim3(3, 18, 2048), 256>>>(h1, (unsigned*)h1q,
        16, 32, 32, 18, 34, 17, 0);

    // L2: M=65536, N=128, K=4096, split-K=2 (wave fill: 1024 CTAs)
    convimma_kernel<<<dim3(512, 1, 2), 512, CI_SMEM>>>(h1q, w2h, w2l, c2p,
        64, 128, 8, 16, 16, 18, 34, 34, 2048, 8388608, 0, 1);
    bnstats_red_kernel<<<128, 256>>>(c2p, c2, g2, b2, 128, 2048, 2, 8388608, 2);
    quantBN_pad_kernel<<<dim3(1, 10, 4096), 256>>>(c2, (unsigned*)c2q,
        127, 8, 16, 16, 10, 18, 9, 2);

    // L3: M=8192, N=256, K=8192, split-K=2
    convimma_kernel<<<dim3(64, 2, 2), 512, CI_SMEM>>>(c2q, w3h, w3l, c3p,
        128, 256, 4, 8, 8, 10, 18, 18, 4096, 2097152, 2, 3);
    bnstats_red_kernel<<<256, 256>>>(c3p, c3, g3, b3, 256, 256, 2, 2097152, 4);
    quantBN_pad_kernel<<<dim3(1, 6, 8192), 256>>>(c3, (unsigned*)c3q,
        255, 4, 8, 8, 6, 10, 5, 4);

    // L4: M=1024, N=512, K=16384, split-K=8
    convimma_kernel<<<dim3(8, 4, 8), 512, CI_SMEM>>>(c3q, w4h, w4l, c4p,
        256, 512, 2, 4, 4, 6, 10, 10, 2048, 524288, 4, 5);
    bnstats_red_kernel<<<512, 256>>>(c4p, c4, g4, b4, 512, 32, 8, 524288, -1);
    bn_lrelu_kernel<<<131072 / 256, 256>>>((float4*)c4, 512, 8, 131072);

    // minibatch discrimination + final
    pairwise_kernel<<<dim3(32, 32), 256>>>();
    final_kernel<<<32, 256>>>(w5, out);
}

// round 15
// speedup vs baseline: 1.0727x; 1.0727x over previous
#include <cuda_runtime.h>
#include <cstdint>

#define DEVFN __device__ __forceinline__

// ---------------------------------------------------------------------------
// Scratch (static device globals — no allocations anywhere)
// Quantized activations stored HALO-PADDED: (IDp=ID+2, IHp=IH+2, IWp=IW+2
// rounded even), left-pad 1, halo = 0 (conv zero-padding materialized).
// ---------------------------------------------------------------------------
__device__ float          g_h1 [33554432u];            // conv1 out fp32
__device__ unsigned short g_h1q[42614784u];            // 32*64*18*34*34
__device__ float          g_c2 [8388608u];
__device__ unsigned short g_c2q[13271040u];            // 32*128*10*18*18
__device__ float          g_c3 [2097152u];
__device__ float          g_c3p[2u * 2097152u];
__device__ unsigned short g_c3q[4915200u];             // 32*256*6*10*10
__device__ float          g_c4 [524288u];
__device__ float          g_c4p[8u * 524288u];
__device__ signed char    g_w2h[524288u],  g_w2l[524288u];
__device__ signed char    g_w3h[2097152u], g_w3l[2097152u];
__device__ signed char    g_w4h[8388608u], g_w4l[8388608u];
__device__ int            g_amax[8];                   // float bits, >= 0
__device__ float          g_bnscale[512];
__device__ float          g_bnshift[512];
__device__ float          g_d[32 * 32];

#define QMAX 32512.0f

// ---------------------------------------------------------------------------
// Helpers
// ---------------------------------------------------------------------------
DEVFN uint32_t smem_u32(const void* p)
{
    uint32_t a;
    asm("{ .reg .u64 t; cvta.to.shared.u64 t, %1; cvt.u32.u64 %0, t; }"
        : "=r"(a) : "l"(p));
    return a;
}

DEVFN void ldsm4(uint32_t* r, uint32_t addr)
{
    asm volatile("ldmatrix.sync.aligned.m8n8.x4.shared.b16 {%0,%1,%2,%3}, [%4];"
                 : "=r"(r[0]), "=r"(r[1]), "=r"(r[2]), "=r"(r[3]) : "r"(addr));
}

DEVFN void imma(int* c, const uint32_t* a, uint32_t b0, uint32_t b1)
{
    asm volatile(
        "mma.sync.aligned.m16n8k32.row.col.s32.s8.s8.s32 "
        "{%0,%1,%2,%3}, {%4,%5,%6,%7}, {%8,%9}, {%0,%1,%2,%3};"
        : "+r"(c[0]), "+r"(c[1]), "+r"(c[2]), "+r"(c[3])
        : "r"(a[0]), "r"(a[1]), "r"(a[2]), "r"(a[3]), "r"(b0), "r"(b1));
}

DEVFN void cpa16(uint32_t dst, const void* src)
{
    asm volatile("cp.async.cg.shared.global [%0], [%1], 16;"
                 :: "r"(dst), "l"(src) : "memory");
}
#define CP_COMMIT() asm volatile("cp.async.commit_group;" ::: "memory")

DEVFN void amax_atomic(int idx, float v)
{
    atomicMax(&g_amax[idx], __float_as_int(v));
}

DEVFN unsigned short quant16(float v, float inv)
{
    float q = rintf(v * inv);
    q = fminf(fmaxf(q, -QMAX), QMAX);
    const int Q = (int)q;
    const int h = (Q + 128) >> 8;          // h in [-127,127]
    const int l = Q - (h << 8);            // l in [-128,127]
    return (unsigned short)(((h & 0xff) << 8) | (l & 0xff));
}

// ---------------------------------------------------------------------------
// Setup kernels (fused across the 3 weight tensors)
// ---------------------------------------------------------------------------
__global__ void zeroamax_kernel()
{
    if (threadIdx.x < 8) g_amax[threadIdx.x] = 0;
}

__global__ void wamax3_kernel(const float4* __restrict__ w2,
                              const float4* __restrict__ w3,
                              const float4* __restrict__ w4)
{
    const int which = blockIdx.y;
    const float4* w = (which == 0) ? w2 : (which == 1) ? w3 : w4;
    const int n4    = (which == 0) ? 131072 : (which == 1) ? 524288 : 2097152;
    const int idx   = (which == 0) ? 1 : (which == 1) ? 3 : 5;

    const int stride = gridDim.x * 256;
    float am = 0.f;
    for (int i = blockIdx.x * 256 + threadIdx.x; i < n4; i += stride) {
        const float4 v = w[i];
        am = fmaxf(am, fmaxf(fmaxf(fabsf(v.x), fabsf(v.y)),
                             fmaxf(fabsf(v.z), fabsf(v.w))));
    }
    __shared__ float sh[256];
    sh[threadIdx.x] = am;
    __syncthreads();
    for (int o = 128; o > 0; o >>= 1) {
        if (threadIdx.x < o) sh[threadIdx.x] = fmaxf(sh[threadIdx.x], sh[threadIdx.x + o]);
        __syncthreads();
    }
    if (threadIdx.x == 0) amax_atomic(idx, sh[0]);
}

__global__ void wquant3_kernel(const float* __restrict__ w2,
                               const float* __restrict__ w3,
                               const float* __restrict__ w4,
                               signed char* __restrict__ o2h, signed char* __restrict__ o2l,
                               signed char* __restrict__ o3h, signed char* __restrict__ o3l,
                               signed char* __restrict__ o4h, signed char* __restrict__ o4l)
{
    const int which = blockIdx.y;
    const float* w = (which == 0) ? w2 : (which == 1) ? w3 : w4;
    signed char* oh = (which == 0) ? o2h : (which == 1) ? o3h : o4h;
    signed char* ol = (which == 0) ? o2l : (which == 1) ? o3l : o4l;
    const int n   = (which == 0) ? 524288 : (which == 1) ? 2097152 : 8388608;
    const int idx = (which == 0) ? 1 : (which == 1) ? 3 : 5;

    const float amax = __int_as_float(g_amax[idx]);
    const float inv = QMAX / fmaxf(amax, 1e-30f);
    const int stride = gridDim.x * 256;
    for (int i = blockIdx.x * 256 + threadIdx.x; i < n; i += stride) {
        const unsigned short q = quant16(w[i], inv);
        oh[i] = (signed char)(q >> 8);
        ol[i] = (signed char)(q & 0xff);
    }
}

// ---------------------------------------------------------------------------
// Padded quantizers, FLAT-indexed (thread -> one u32 = 2 elements).
// ---------------------------------------------------------------------------
__global__ void quantA_pad_kernel(const float* __restrict__ in,
                                  unsigned* __restrict__ out,
                                  int ID, int IH, int IW,
                                  int IDp, int IHp, int IWp2, int amaxIdx)
{
    const int hw = blockIdx.x * 256 + threadIdx.x;
    const int HW = IHp * IWp2;
    if (hw >= HW) return;
    const int hp = hw / IWp2;
    const int w2 = hw - hp * IWp2;
    const int dp = blockIdx.y;
    const int z  = blockIdx.z;

    const float amax = __int_as_float(g_amax[amaxIdx]);
    const float inv = QMAX / fmaxf(amax, 1e-30f);

    float v0 = 0.f, v1 = 0.f;
    if (dp >= 1 && dp <= ID && hp >= 1 && hp <= IH) {
        const size_t srcrow = (((size_t)z * ID + (dp - 1)) * IH + (hp - 1)) * IW;
        const int wp0 = 2 * w2;
        if (wp0 >= 1 && wp0 <= IW) v0 = in[srcrow + wp0 - 1];
        if (wp0 + 1 <= IW)         v1 = in[srcrow + wp0];
    }
    out[((size_t)z * IDp + dp) * HW + hw] =
        (unsigned)quant16(v0, inv) | ((unsigned)quant16(v1, inv) << 16);
}

__global__ void quantBN_pad_kernel(const float* __restrict__ in,
                                   unsigned* __restrict__ out,
                                   int Cmask, int ID, int IH, int IW,
                                   int IDp, int IHp, int IWp2, int amaxIdx)
{
    const int hw = blockIdx.x * 256 + threadIdx.x;
    const int HW = IHp * IWp2;
    if (hw >= HW) return;
    const int hp = hw / IWp2;
    const int w2 = hw - hp * IWp2;
    const int dp = blockIdx.y;
    const int z  = blockIdx.z;
    const int c  = z & Cmask;

    const float sc = g_bnscale[c], sh = g_bnshift[c];
    const float amax = __int_as_float(g_amax[amaxIdx]);
    const float inv = QMAX / fmaxf(amax, 1e-30f);

    float v0 = 0.f, v1 = 0.f;
    if (dp >= 1 && dp <= ID && hp >= 1 && hp <= IH) {
        const size_t srcrow = (((size_t)z * ID + (dp - 1)) * IH + (hp - 1)) * IW;
        const int wp0 = 2 * w2;
        if (wp0 >= 1 && wp0 <= IW) {
            float v = in[srcrow + wp0 - 1] * sc + sh;
            v0 = (v >= 0.f) ? v : 0.2f * v;
        }
        if (wp0 + 1 <= IW) {
            float v = in[srcrow + wp0] * sc + sh;
            v1 = (v >= 0.f) ? v : 0.2f * v;
        }
    }
    out[((size_t)z * IDp + dp) * HW + hw] =
        (unsigned)quant16(v0, inv) | ((unsigned)quant16(v1, inv) << 16);
}

// ---------------------------------------------------------------------------
// Layer 1: conv3d (64,1,2,4,4), stride (2,2,2), pad (0,1,1), fused lrelu.
// Direct LDG version (faster than smem staging: L1-resident loads, 2x occ).
// ---------------------------------------------------------------------------
__global__ __launch_bounds__(1024, 1)
void conv1_kernel(const float* __restrict__ x, const float* __restrict__ w1)
{
    __shared__ float ws[2048];
    __shared__ float sm[1024];
    const int t = threadIdx.x;
    for (int i = t; i < 2048; i += 1024) ws[i] = w1[i];
    __syncthreads();

    const int od = blockIdx.x;
    const int n  = blockIdx.y;
    const int oh = t >> 5;
    const int ow = t & 31;

    const float* xb = x + (size_t)n * 131072 + (size_t)(od * 2) * 4096;
    const int ih0 = oh * 2 - 1;
    const int iw0 = ow * 2 - 1;

    float v[32];
#pragma unroll
    for (int kd = 0; kd < 2; ++kd)
#pragma unroll
        for (int kh = 0; kh < 4; ++kh)
#pragma unroll
            for (int kw = 0; kw < 4; ++kw) {
                const int ih = ih0 + kh, iw = iw0 + kw;
                const bool ok = ((unsigned)ih < 64u) && ((unsigned)iw < 64u);
                v[kd * 16 + kh * 4 + kw] = ok ? xb[kd * 4096 + ih * 64 + iw] : 0.f;
            }

    float* outb = g_h1 + ((size_t)(n * 64) * 16 + od) * 1024 + t;
    float am = 0.f;
#pragma unroll 4
    for (int c = 0; c < 64; ++c) {
        const float4* wp = (const float4*)&ws[c * 32];
        float acc = 0.f;
#pragma unroll
        for (int q = 0; q < 8; ++q) {
            const float4 w4 = wp[q];
            acc += v[q * 4 + 0] * w4.x + v[q * 4 + 1] * w4.y
                 + v[q * 4 + 2] * w4.z + v[q * 4 + 3] * w4.w;
        }
        acc = (acc >= 0.f) ? acc : 0.2f * acc;
        am = fmaxf(am, fabsf(acc));
        outb[(size_t)c * 16384] = acc;
    }

    sm[t] = am;
    __syncthreads();
    for (int o = 512; o > 0; o >>= 1) {
        if (t < o) sm[t] = fmaxf(sm[t], sm[t + o]);
        __syncthreads();
    }
    if (t == 0) amax_atomic(0, sm[0]);
}

// ---------------------------------------------------------------------------
// int8 IMMA implicit-GEMM conv3d, HALO-PADDED input, K-CHUNK 64.
// CTA 128x128, 16 warps (4x4), warp tile 32x32. 3-stage pipeline.
// ---------------------------------------------------------------------------
#define ROWB 80
#define TILE (128 * ROWB)
#define BUF  (4 * TILE)
#define CI_SMEM (3 * BUF)     // 122880 B

__global__ __launch_bounds__(512, 1)
void convimma_kernel(const unsigned short* __restrict__ inq,
                     const signed char* __restrict__ wh,
                     const signed char* __restrict__ wl,
                     float* __restrict__ out,
                     int Cin, int Cout, int OD, int OH, int OW,
                     int IDp, int IHp, int IWp,
                     int kPerSplit, int sliceElems, int iaIdx, int ibIdx)
{
    extern __shared__ unsigned char dsm[];
    const uint32_t smb = smem_u32(dsm);

    const int t    = threadIdx.x;
    const int lane = t & 31;
    const int wid  = t >> 5;
    const int mw   = (wid & 3) * 32;
    const int nww  = (wid >> 2) * 32;

    const int OHW  = OH * OW;
    const int ODHW = OD * OHW;
    const int IHWp = IHp * IWp;
    const int IWp2 = IWp >> 1;
    const int K    = Cin * 64;

    const int mBase = blockIdx.x * 128;
    const int cBase = blockIdx.y * 128;
    const int kBase = blockIdx.z * kPerSplit;

    const int lm = t >> 2;
    const int kq = t & 3;
    const int mload = mBase + lm;
    const int n_l = mload / ODHW;
    int srem = mload % ODHW;
    const int od = srem / OHW; srem %= OHW;
    const int oh = srem / OW;
    const int ow = srem % OW;

    const int rowElem0 = (oh * 2) * IWp + 2 * ow;
    const uint32_t aOff = (uint32_t)(lm * ROWB + kq * 16);

    const int brow = t & 127;
    const int bpl  = (t >> 7) & 1;
    const int bh2  = (t >> 8) & 1;
    const signed char* wsrc = (bpl ? wl : wh) + (size_t)(cBase + brow) * K
                            + kBase + bh2 * 32;
    const uint32_t bDst = (uint32_t)((2 + bpl) * TILE + brow * ROWB + bh2 * 32);

    const uint32_t lrow = (lane & 15);
    const uint32_t lsel = (lane >> 4) * 16;

    int acc_hh[2][4][4], acc_md[2][4][4];
#pragma unroll
    for (int a = 0; a < 2; ++a)
#pragma unroll
        for (int b = 0; b < 4; ++b)
#pragma unroll
            for (int q = 0; q < 4; ++q) { acc_hh[a][b][q] = 0; acc_md[a][b][q] = 0; }

    const int nCh = kPerSplit >> 6;

    unsigned wA[8];
    auto gatherA = [&](int kc) {
        const int cin = (kBase >> 6) + kc;
        const int idp = od * 2 + kq;
        const unsigned* p = (const unsigned*)(inq
            + ((size_t)(n_l * Cin + cin) * IDp + idp) * IHWp + rowElem0);
#pragma unroll
        for (int kh = 0; kh < 4; ++kh) {
            wA[2 * kh]     = p[kh * IWp2];
            wA[2 * kh + 1] = p[kh * IWp2 + 1];
        }
    };

    auto cpasyncB = [&](int kc, int buf) {
        const uint32_t d = smb + buf * BUF + bDst;
        const signed char* s = wsrc + ((size_t)kc << 6);
        cpa16(d, s);
        cpa16(d + 16, s + 16);
        CP_COMMIT();
    };

    auto storeA = [&](int buf) {
        unsigned char* base = dsm + buf * BUF + aOff;
        uint4 hi, lo;
        hi.x = __byte_perm(wA[0], wA[1], 0x7531);
        lo.x = __byte_perm(wA[0], wA[1], 0x6420);
        hi.y = __byte_perm(wA[2], wA[3], 0x7531);
        lo.y = __byte_perm(wA[2], wA[3], 0x6420);
        hi.z = __byte_perm(wA[4], wA[5], 0x7531);
        lo.z = __byte_perm(wA[4], wA[5], 0x6420);
        hi.w = __byte_perm(wA[6], wA[7], 0x7531);
        lo.w = __byte_perm(wA[6], wA[7], 0x6420);
        *(uint4*)(base)        = hi;
        *(uint4*)(base + TILE) = lo;
    };

    gatherA(0);
    cpasyncB(0, 0);
    storeA(0);
    gatherA(1);
    cpasyncB(1, 1);
    storeA(1);

    for (int kc = 0; kc < nCh; ++kc) {
        const int pf = kc + 2;

        if (kc + 1 < nCh)
            asm volatile("cp.async.wait_group 1;" ::: "memory");
        else
            asm volatile("cp.async.wait_group 0;" ::: "memory");
        __syncthreads();

        if (pf < nCh) { cpasyncB(pf, pf % 3); gatherA(pf); }

        const uint32_t aH = smb + (kc % 3) * BUF;
        const uint32_t aL = aH + TILE;
        const uint32_t bH = aH + 2 * TILE;
        const uint32_t bL = aH + 3 * TILE;

#pragma unroll
        for (int ks = 0; ks < 2; ++ks) {
            const uint32_t sel = lsel + ks * 32;
            uint32_t ah[2][4], al[2][4], bh[2][4], bl[2][4];
#pragma unroll
            for (int tm = 0; tm < 2; ++tm) {
                const uint32_t ro = (uint32_t)(mw + tm * 16 + lrow) * ROWB + sel;
                ldsm4(ah[tm], aH + ro);
                ldsm4(al[tm], aL + ro);
            }
#pragma unroll
            for (int bt = 0; bt < 2; ++bt) {
                const uint32_t ro = (uint32_t)(nww + bt * 16 + lrow) * ROWB + sel;
                ldsm4(bh[bt], bH + ro);
                ldsm4(bl[bt], bL + ro);
            }
#pragma unroll
            for (int tm = 0; tm < 2; ++tm)
#pragma unroll
                for (int bt = 0; bt < 2; ++bt)
#pragma unroll
                    for (int sub = 0; sub < 2; ++sub) {
                        const int tn = bt * 2 + sub;
                        imma(acc_hh[tm][tn], ah[tm], bh[bt][sub], bh[bt][sub + 2]);
                        imma(acc_md[tm][tn], ah[tm], bl[bt][sub], bl[bt][sub + 2]);
                        imma(acc_md[tm][tn], al[tm], bh[bt][sub], bh[bt][sub + 2]);
                    }
        }

        if (pf < nCh) storeA(pf % 3);
    }

    // ---- epilogue ----
    const float amA = __int_as_float(g_amax[iaIdx]);
    const float amB = __int_as_float(g_amax[ibIdx]);
    const float sAB = (amA / QMAX) * (amB / QMAX);

    float* outz = out + (size_t)blockIdx.z * sliceElems;
#pragma unroll
    for (int tm = 0; tm < 2; ++tm) {
#pragma unroll
        for (int half = 0; half < 2; ++half) {
            const int m   = mBase + mw + tm * 16 + (lane >> 2) + 8 * half;
            const int n_o = m / ODHW;
            const int s_o = m % ODHW;
            float* ob = outz + (size_t)(n_o * Cout + cBase) * ODHW + s_o;
#pragma unroll
            for (int tn = 0; tn < 4; ++tn) {
                const int col = nww + tn * 8 + 2 * (lane & 3);
                const float v0 = sAB * fmaf(65536.f,
                    (float)acc_hh[tm][tn][half * 2 + 0],
                    256.f * (float)acc_md[tm][tn][half * 2 + 0]);
                const float v1 = sAB * fmaf(65536.f,
                    (float)acc_hh[tm][tn][half * 2 + 1],
                    256.f * (float)acc_md[tm][tn][half * 2 + 1]);
                ob[(size_t)col * ODHW]       = v0;
                ob[(size_t)(col + 1) * ODHW] = v1;
            }
        }
    }
}

// ---------------------------------------------------------------------------
// BatchNorm stats, single pass over a non-split tensor (+ activated amax).
// ---------------------------------------------------------------------------
__global__ void bn_stats_kernel(const float* __restrict__ in,
                                const float* __restrict__ g,
                                const float* __restrict__ b,
                                int C, int ODHW, int amaxIdx)
{
    const int c = blockIdx.x;
    const int t = threadIdx.x;
    double s = 0.0, s2 = 0.0;
    float mn = 3.0e38f, mx = -3.0e38f;
    for (int n = 0; n < 32; ++n) {
        const float* base = in + (size_t)(n * C + c) * ODHW;
        for (int sp = t; sp < ODHW; sp += 256) {
            const float f = base[sp];
            const double v = (double)f;
            s += v; s2 += v * v;
            mn = fminf(mn, f); mx = fmaxf(mx, f);
        }
    }
    __shared__ double sh[256], sh2[256];
    __shared__ float smn[256], smx[256];
    sh[t] = s; sh2[t] = s2; smn[t] = mn; smx[t] = mx;
    __syncthreads();
    for (int o = 128; o > 0; o >>= 1) {
        if (t < o) {
            sh[t] += sh[t + o]; sh2[t] += sh2[t + o];
            smn[t] = fminf(smn[t], smn[t + o]);
            smx[t] = fmaxf(smx[t], smx[t + o]);
        }
        __syncthreads();
    }
    if (t == 0) {
        const double cnt  = 32.0 * (double)ODHW;
        const double mean = sh[0] / cnt;
        const double var  = sh2[0] / cnt - mean * mean;
        const double scd  = (double)g[c] / sqrt(var + 1e-5);
        const float sc = (float)scd;
        const float shv = (float)((double)b[c] - mean * scd);
        g_bnscale[c] = sc;
        g_bnshift[c] = shv;
        if (amaxIdx >= 0) {
            float a1 = smx[0] * sc + shv; a1 = (a1 >= 0.f) ? a1 : 0.2f * a1;
            float a2 = smn[0] * sc + shv; a2 = (a2 >= 0.f) ? a2 : 0.2f * a2;
            amax_atomic(amaxIdx, fmaxf(fabsf(a1), fabsf(a2)));
        }
    }
}

// ---------------------------------------------------------------------------
// Fused split-K reduction + BatchNorm stats (small tensors: conv3/conv4).
// Sums nSlices partials (left-to-right, same order as the old reduce
// kernels), writes the reduced tensor, and computes stats + activated amax.
// ---------------------------------------------------------------------------
__global__ void bnstats_red_kernel(const float* __restrict__ partials,
                                   float* __restrict__ outbuf,
                                   const float* __restrict__ g,
                                   const float* __restrict__ b,
                                   int C, int ODHW, int nSlices, int sliceElems,
                                   int amaxIdx)
{
    const int c = blockIdx.x;
    const int t = threadIdx.x;
    double s = 0.0, s2 = 0.0;
    float mn = 3.0e38f, mx = -3.0e38f;
    for (int n = 0; n < 32; ++n) {
        const size_t base = ((size_t)n * C + c) * ODHW;
        for (int sp = t; sp < ODHW; sp += 256) {
            const size_t off = base + sp;
            float f = partials[off];
            for (int z = 1; z < nSlices; ++z)
                f += partials[off + (size_t)z * sliceElems];
            outbuf[off] = f;
            const double v = (double)f;
            s += v; s2 += v * v;
            mn = fminf(mn, f); mx = fmaxf(mx, f);
        }
    }
    __shared__ double sh[256], sh2[256];
    __shared__ float smn[256], smx[256];
    sh[t] = s; sh2[t] = s2; smn[t] = mn; smx[t] = mx;
    __syncthreads();
    for (int o = 128; o > 0; o >>= 1) {
        if (t < o) {
            sh[t] += sh[t + o]; sh2[t] += sh2[t + o];
            smn[t] = fminf(smn[t], smn[t + o]);
            smx[t] = fmaxf(smx[t], smx[t + o]);
        }
        __syncthreads();
    }
    if (t == 0) {
        const double cnt  = 32.0 * (double)ODHW;
        const double mean = sh[0] / cnt;
        const double var  = sh2[0] / cnt - mean * mean;
        const double scd  = (double)g[c] / sqrt(var + 1e-5);
        const float sc = (float)scd;
        const float shv = (float)((double)b[c] - mean * scd);
        g_bnscale[c] = sc;
        g_bnshift[c] = shv;
        if (amaxIdx >= 0) {
            float a1 = smx[0] * sc + shv; a1 = (a1 >= 0.f) ? a1 : 0.2f * a1;
            float a2 = smn[0] * sc + shv; a2 = (a2 >= 0.f) ? a2 : 0.2f * a2;
            amax_atomic(amaxIdx, fmaxf(fabsf(a1), fabsf(a2)));
        }
    }
}

// ---------------------------------------------------------------------------
// BN apply + lrelu in place (fp32, conv4 output).
// ---------------------------------------------------------------------------
__global__ void bn_lrelu_kernel(float4* __restrict__ x, int C, int ODHW4, int total4)
{
    const int i = blockIdx.x * 256 + threadIdx.x;
    if (i >= total4) return;
    const int c = (i / ODHW4) % C;
    const float sc = g_bnscale[c], sh = g_bnshift[c];
    float4 v = x[i];
    v.x = v.x * sc + sh; v.x = (v.x >= 0.f) ? v.x : 0.2f * v.x;
    v.y = v.y * sc + sh; v.y = (v.y >= 0.f) ? v.y : 0.2f * v.y;
    v.z = v.z * sc + sh; v.z = (v.z >= 0.f) ? v.z : 0.2f * v.z;
    v.w = v.w * sc + sh; v.w = (v.w >= 0.f) ? v.w : 0.2f * v.w;
    x[i] = v;
}

// ---------------------------------------------------------------------------
// Minibatch discrimination + final reduction.
// ---------------------------------------------------------------------------
__global__ void pairwise_kernel()
{
    const int i = blockIdx.y, j = blockIdx.x, t = threadIdx.x;
    const float* a = g_c4 + (size_t)i * 16384;
    const float* b = g_c4 + (size_t)j * 16384;
    float s = 0.f;
    for (int k = t; k < 16384; k += 256) s += fabsf(a[k] - b[k]);
    __shared__ float sh[256];
    sh[t] = s;
    __syncthreads();
    for (int o = 128; o > 0; o >>= 1) {
        if (t < o) sh[t] += sh[t + o];
        __syncthreads();
    }
    if (t == 0)
        g_d[i * 32 + j] = sh[0] * (1.f / 16384.f) + ((i == j) ? 1e6f : 0.f);
}

__global__ void final_kernel(const float* __restrict__ w5, float* __restrict__ out)
{
    const int n = blockIdx.x, t = threadIdx.x;

    __shared__ float shm[256];
    shm[t] = (t < 32) ? g_d[n * 32 + t] : 1e30f;
    __syncthreads();
    for (int o = 128; o > 0; o >>= 1) {
        if (t < o) shm[t] = fminf(shm[t], shm[t + o]);
        __syncthreads();
    }
    const float s = shm[0];
    __syncthreads();

    double acc = 0.0;
    const float* h = g_c4 + (size_t)n * 16384;
    for (int k = t; k < 16384; k += 256)
        acc += (double)h[k] * (double)w5[k];
    if (t < 32)
        acc += (double)s * (double)w5[16384 + t];

    __shared__ double shd[256];
    shd[t] = acc;
    __syncthreads();
    for (int o = 128; o > 0; o >>= 1) {
        if (t < o) shd[t] += shd[t + o];
        __syncthreads();
    }
    if (t == 0) out[n] = (float)shd[0];
}

// ---------------------------------------------------------------------------
// Launch chain. Inputs: x, w1, w2, g2, b2, w3, g3, b3, w4, g4, b4, w5
// ---------------------------------------------------------------------------
extern "C" void kernel_launch(void* const* d_in, const int* in_sizes, int n_in,
                              void* d_out, int out_size)
{
    (void)in_sizes; (void)n_in; (void)out_size;
    const float* x  = (const float*)d_in[0];
    const float* w1 = (const float*)d_in[1];
    const float* w2 = (const float*)d_in[2];
    const float* g2 = (const float*)d_in[3];
    const float* b2 = (const float*)d_in[4];
    const float* w3 = (const float*)d_in[5];
    const float* g3 = (const float*)d_in[6];
    const float* b3 = (const float*)d_in[7];
    const float* w4 = (const float*)d_in[8];
    const float* g4 = (const float*)d_in[9];
    const float* b4 = (const float*)d_in[10];
    const float* w5 = (const float*)d_in[11];
    float* out = (float*)d_out;

    float *h1, *c2, *c3, *c3p, *c4, *c4p;
    unsigned short *h1q, *c2q, *c3q;
    signed char *w2h, *w2l, *w3h, *w3l, *w4h, *w4l;
    cudaGetSymbolAddress((void**)&h1,  g_h1);
    cudaGetSymbolAddress((void**)&h1q, g_h1q);
    cudaGetSymbolAddress((void**)&c2,  g_c2);
    cudaGetSymbolAddress((void**)&c2q, g_c2q);
    cudaGetSymbolAddress((void**)&c3,  g_c3);
    cudaGetSymbolAddress((void**)&c3p, g_c3p);
    cudaGetSymbolAddress((void**)&c3q, g_c3q);
    cudaGetSymbolAddress((void**)&c4,  g_c4);
    cudaGetSymbolAddress((void**)&c4p, g_c4p);
    cudaGetSymbolAddress((void**)&w2h, g_w2h);
    cudaGetSymbolAddress((void**)&w2l, g_w2l);
    cudaGetSymbolAddress((void**)&w3h, g_w3h);
    cudaGetSymbolAddress((void**)&w3l, g_w3l);
    cudaGetSymbolAddress((void**)&w4h, g_w4h);
    cudaGetSymbolAddress((void**)&w4l, g_w4l);

    cudaFuncSetAttribute(convimma_kernel,
                         cudaFuncAttributeMaxDynamicSharedMemorySize, CI_SMEM);

    // amax init + fused weight amax/quant
    zeroamax_kernel<<<1, 32>>>();
    wamax3_kernel<<<dim3(256, 3), 256>>>((const float4*)w2, (const float4*)w3,
                                         (const float4*)w4);
    wquant3_kernel<<<dim3(4096, 3), 256>>>(w2, w3, w4,
                                           w2h, w2l, w3h, w3l, w4h, w4l);

    // L1 + padded quantize (h1: 16,32,32 -> 18,34,34; IWp2=17)
    conv1_kernel<<<dim3(16, 32), 1024>>>(x, w1);
    quantA_pad_kernel<<<dim3(3, 18, 2048), 256>>>(h1, (unsigned*)h1q,
        16, 32, 32, 18, 34, 17, 0);

    // L2: M=65536, N=128, K=4096 (no split-K: partial traffic outweighs tail)
    convimma_kernel<<<dim3(512, 1, 1), 512, CI_SMEM>>>(h1q, w2h, w2l, c2,
        64, 128, 8, 16, 16, 18, 34, 34, 4096, 0, 0, 1);
    bn_stats_kernel<<<128, 256>>>(c2, g2, b2, 128, 2048, 2);
    quantBN_pad_kernel<<<dim3(1, 10, 4096), 256>>>(c2, (unsigned*)c2q,
        127, 8, 16, 16, 10, 18, 9, 2);

    // L3: M=8192, N=256, K=8192, split-K=2; fused reduce+stats
    convimma_kernel<<<dim3(64, 2, 2), 512, CI_SMEM>>>(c2q, w3h, w3l, c3p,
        128, 256, 4, 8, 8, 10, 18, 18, 4096, 2097152, 2, 3);
    bnstats_red_kernel<<<256, 256>>>(c3p, c3, g3, b3, 256, 256, 2, 2097152, 4);
    quantBN_pad_kernel<<<dim3(1, 6, 8192), 256>>>(c3, (unsigned*)c3q,
        255, 4, 8, 8, 6, 10, 5, 4);

    // L4: M=1024, N=512, K=16384, split-K=8; fused reduce+stats
    convimma_kernel<<<dim3(8, 4, 8), 512, CI_SMEM>>>(c3q, w4h, w4l, c4p,
        256, 512, 2, 4, 4, 6, 10, 10, 2048, 524288, 4, 5);
    bnstats_red_kernel<<<512, 256>>>(c4p, c4, g4, b4, 512, 32, 8, 524288, -1);
    bn_lrelu_kernel<<<131072 / 256, 256>>>((float4*)c4, 512, 8, 131072);

    // minibatch discrimination + final
    pairwise_kernel<<<dim3(32, 32), 256>>>();
    final_kernel<<<32, 256>>>(w5, out);
}

// round 16
// speedup vs baseline: 1.0889x; 1.0151x over previous
#include <cuda_runtime.h>
#include <cstdint>

#define DEVFN __device__ __forceinline__

// ---------------------------------------------------------------------------
// Scratch (static device globals — no allocations anywhere)
// Quantized activations stored HALO-PADDED: (IDp=ID+2, IHp=IH+2, IWp=IW+2
// rounded even), left-pad 1, halo = 0 (conv zero-padding materialized).
// ---------------------------------------------------------------------------
__device__ float          g_h1 [33554432u];            // conv1 out fp32
__device__ unsigned short g_h1q[42614784u];            // 32*64*18*34*34
__device__ float          g_c2 [8388608u];
__device__ unsigned short g_c2q[13271040u];            // 32*128*10*18*18
__device__ float          g_c3 [2097152u];
__device__ float          g_c3p[2u * 2097152u];
__device__ unsigned short g_c3q[4915200u];             // 32*256*6*10*10
__device__ float          g_c4 [524288u];
__device__ float          g_c4p[8u * 524288u];
__device__ signed char    g_w2h[524288u],  g_w2l[524288u];
__device__ signed char    g_w3h[2097152u], g_w3l[2097152u];
__device__ signed char    g_w4h[8388608u], g_w4l[8388608u];
__device__ int            g_amax[8];                   // float bits, >= 0
__device__ float          g_bnscale[512];
__device__ float          g_bnshift[512];
__device__ float          g_d[32 * 32];

#define QMAX 32512.0f

// ---------------------------------------------------------------------------
// Helpers
// ---------------------------------------------------------------------------
DEVFN uint32_t smem_u32(const void* p)
{
    uint32_t a;
    asm("{ .reg .u64 t; cvta.to.shared.u64 t, %1; cvt.u32.u64 %0, t; }"
        : "=r"(a) : "l"(p));
    return a;
}

DEVFN void ldsm4(uint32_t* r, uint32_t addr)
{
    asm volatile("ldmatrix.sync.aligned.m8n8.x4.shared.b16 {%0,%1,%2,%3}, [%4];"
                 : "=r"(r[0]), "=r"(r[1]), "=r"(r[2]), "=r"(r[3]) : "r"(addr));
}

DEVFN void imma(int* c, const uint32_t* a, uint32_t b0, uint32_t b1)
{
    asm volatile(
        "mma.sync.aligned.m16n8k32.row.col.s32.s8.s8.s32 "
        "{%0,%1,%2,%3}, {%4,%5,%6,%7}, {%8,%9}, {%0,%1,%2,%3};"
        : "+r"(c[0]), "+r"(c[1]), "+r"(c[2]), "+r"(c[3])
        : "r"(a[0]), "r"(a[1]), "r"(a[2]), "r"(a[3]), "r"(b0), "r"(b1));
}

DEVFN void cpa16(uint32_t dst, const void* src)
{
    asm volatile("cp.async.cg.shared.global [%0], [%1], 16;"
                 :: "r"(dst), "l"(src) : "memory");
}
#define CP_COMMIT() asm volatile("cp.async.commit_group;" ::: "memory")

DEVFN void amax_atomic(int idx, float v)
{
    atomicMax(&g_amax[idx], __float_as_int(v));
}

DEVFN unsigned short quant16(float v, float inv)
{
    float q = rintf(v * inv);
    q = fminf(fmaxf(q, -QMAX), QMAX);
    const int Q = (int)q;
    const int h = (Q + 128) >> 8;          // h in [-127,127]
    const int l = Q - (h << 8);            // l in [-128,127]
    return (unsigned short)(((h & 0xff) << 8) | (l & 0xff));
}

// ---------------------------------------------------------------------------
// Setup kernels (fused across the 3 weight tensors)
// ---------------------------------------------------------------------------
__global__ void zeroamax_kernel()
{
    if (threadIdx.x < 8) g_amax[threadIdx.x] = 0;
}

__global__ void wamax3_kernel(const float4* __restrict__ w2,
                              const float4* __restrict__ w3,
                              const float4* __restrict__ w4)
{
    const int which = blockIdx.y;
    const float4* w = (which == 0) ? w2 : (which == 1) ? w3 : w4;
    const int n4    = (which == 0) ? 131072 : (which == 1) ? 524288 : 2097152;
    const int idx   = (which == 0) ? 1 : (which == 1) ? 3 : 5;

    const int stride = gridDim.x * 256;
    float am = 0.f;
    for (int i = blockIdx.x * 256 + threadIdx.x; i < n4; i += stride) {
        const float4 v = w[i];
        am = fmaxf(am, fmaxf(fmaxf(fabsf(v.x), fabsf(v.y)),
                             fmaxf(fabsf(v.z), fabsf(v.w))));
    }
    __shared__ float sh[256];
    sh[threadIdx.x] = am;
    __syncthreads();
    for (int o = 128; o > 0; o >>= 1) {
        if (threadIdx.x < o) sh[threadIdx.x] = fmaxf(sh[threadIdx.x], sh[threadIdx.x + o]);
        __syncthreads();
    }
    if (threadIdx.x == 0) amax_atomic(idx, sh[0]);
}

__global__ void wquant3_kernel(const float* __restrict__ w2,
                               const float* __restrict__ w3,
                               const float* __restrict__ w4,
                               signed char* __restrict__ o2h, signed char* __restrict__ o2l,
                               signed char* __restrict__ o3h, signed char* __restrict__ o3l,
                               signed char* __restrict__ o4h, signed char* __restrict__ o4l)
{
    const int which = blockIdx.y;
    const float* w = (which == 0) ? w2 : (which == 1) ? w3 : w4;
    signed char* oh = (which == 0) ? o2h : (which == 1) ? o3h : o4h;
    signed char* ol = (which == 0) ? o2l : (which == 1) ? o3l : o4l;
    const int n   = (which == 0) ? 524288 : (which == 1) ? 2097152 : 8388608;
    const int idx = (which == 0) ? 1 : (which == 1) ? 3 : 5;

    const float amax = __int_as_float(g_amax[idx]);
    const float inv = QMAX / fmaxf(amax, 1e-30f);
    const int stride = gridDim.x * 256;
    for (int i = blockIdx.x * 256 + threadIdx.x; i < n; i += stride) {
        const unsigned short q = quant16(w[i], inv);
        oh[i] = (signed char)(q >> 8);
        ol[i] = (signed char)(q & 0xff);
    }
}

// ---------------------------------------------------------------------------
// Padded quantizers, FLAT-indexed (thread -> one u32 = 2 elements).
// ---------------------------------------------------------------------------
__global__ void quantA_pad_kernel(const float* __restrict__ in,
                                  unsigned* __restrict__ out,
                                  int ID, int IH, int IW,
                                  int IDp, int IHp, int IWp2, int amaxIdx)
{
    const int hw = blockIdx.x * 256 + threadIdx.x;
    const int HW = IHp * IWp2;
    if (hw >= HW) return;
    const int hp = hw / IWp2;
    const int w2 = hw - hp * IWp2;
    const int dp = blockIdx.y;
    const int z  = blockIdx.z;

    const float amax = __int_as_float(g_amax[amaxIdx]);
    const float inv = QMAX / fmaxf(amax, 1e-30f);

    float v0 = 0.f, v1 = 0.f;
    if (dp >= 1 && dp <= ID && hp >= 1 && hp <= IH) {
        const size_t srcrow = (((size_t)z * ID + (dp - 1)) * IH + (hp - 1)) * IW;
        const int wp0 = 2 * w2;
        if (wp0 >= 1 && wp0 <= IW) v0 = in[srcrow + wp0 - 1];
        if (wp0 + 1 <= IW)         v1 = in[srcrow + wp0];
    }
    out[((size_t)z * IDp + dp) * HW + hw] =
        (unsigned)quant16(v0, inv) | ((unsigned)quant16(v1, inv) << 16);
}

__global__ void quantBN_pad_kernel(const float* __restrict__ in,
                                   unsigned* __restrict__ out,
                                   int Cmask, int ID, int IH, int IW,
                                   int IDp, int IHp, int IWp2, int amaxIdx)
{
    const int hw = blockIdx.x * 256 + threadIdx.x;
    const int HW = IHp * IWp2;
    if (hw >= HW) return;
    const int hp = hw / IWp2;
    const int w2 = hw - hp * IWp2;
    const int dp = blockIdx.y;
    const int z  = blockIdx.z;
    const int c  = z & Cmask;

    const float sc = g_bnscale[c], sh = g_bnshift[c];
    const float amax = __int_as_float(g_amax[amaxIdx]);
    const float inv = QMAX / fmaxf(amax, 1e-30f);

    float v0 = 0.f, v1 = 0.f;
    if (dp >= 1 && dp <= ID && hp >= 1 && hp <= IH) {
        const size_t srcrow = (((size_t)z * ID + (dp - 1)) * IH + (hp - 1)) * IW;
        const int wp0 = 2 * w2;
        if (wp0 >= 1 && wp0 <= IW) {
            float v = in[srcrow + wp0 - 1] * sc + sh;
            v0 = (v >= 0.f) ? v : 0.2f * v;
        }
        if (wp0 + 1 <= IW) {
            float v = in[srcrow + wp0] * sc + sh;
            v1 = (v >= 0.f) ? v : 0.2f * v;
        }
    }
    out[((size_t)z * IDp + dp) * HW + hw] =
        (unsigned)quant16(v0, inv) | ((unsigned)quant16(v1, inv) << 16);
}

// ---------------------------------------------------------------------------
// Layer 1: conv3d (64,1,2,4,4), stride (2,2,2), pad (0,1,1), fused lrelu.
// ---------------------------------------------------------------------------
__global__ __launch_bounds__(1024, 1)
void conv1_kernel(const float* __restrict__ x, const float* __restrict__ w1)
{
    __shared__ float ws[2048];
    __shared__ float sm[1024];
    const int t = threadIdx.x;
    for (int i = t; i < 2048; i += 1024) ws[i] = w1[i];
    __syncthreads();

    const int od = blockIdx.x;
    const int n  = blockIdx.y;
    const int oh = t >> 5;
    const int ow = t & 31;

    const float* xb = x + (size_t)n * 131072 + (size_t)(od * 2) * 4096;
    const int ih0 = oh * 2 - 1;
    const int iw0 = ow * 2 - 1;

    float v[32];
#pragma unroll
    for (int kd = 0; kd < 2; ++kd)
#pragma unroll
        for (int kh = 0; kh < 4; ++kh)
#pragma unroll
            for (int kw = 0; kw < 4; ++kw) {
                const int ih = ih0 + kh, iw = iw0 + kw;
                const bool ok = ((unsigned)ih < 64u) && ((unsigned)iw < 64u);
                v[kd * 16 + kh * 4 + kw] = ok ? xb[kd * 4096 + ih * 64 + iw] : 0.f;
            }

    float* outb = g_h1 + ((size_t)(n * 64) * 16 + od) * 1024 + t;
    float am = 0.f;
#pragma unroll 4
    for (int c = 0; c < 64; ++c) {
        const float4* wp = (const float4*)&ws[c * 32];
        float acc = 0.f;
#pragma unroll
        for (int q = 0; q < 8; ++q) {
            const float4 w4 = wp[q];
            acc += v[q * 4 + 0] * w4.x + v[q * 4 + 1] * w4.y
                 + v[q * 4 + 2] * w4.z + v[q * 4 + 3] * w4.w;
        }
        acc = (acc >= 0.f) ? acc : 0.2f * acc;
        am = fmaxf(am, fabsf(acc));
        outb[(size_t)c * 16384] = acc;
    }

    sm[t] = am;
    __syncthreads();
    for (int o = 512; o > 0; o >>= 1) {
        if (t < o) sm[t] = fmaxf(sm[t], sm[t + o]);
        __syncthreads();
    }
    if (t == 0) amax_atomic(0, sm[0]);
}

// ---------------------------------------------------------------------------
// int8 IMMA implicit-GEMM conv3d, HALO-PADDED input, K-CHUNK 64.
// CTA 128x64, 256 threads (8 warps, 4x2), warp tile 32x32 -> 2 CTAs/SM so
// barrier/wait bubbles of one CTA are covered by the other.
// 3-stage pipeline, one barrier per chunk (CUTLASS ordering).
// ---------------------------------------------------------------------------
#define ROWB   80
#define TILE_A (128 * ROWB)              // 10240 B
#define TILE_B (64 * ROWB)               //  5120 B
#define BUF    (2 * TILE_A + 2 * TILE_B) // 30720 B: Ah, Al, Bh, Bl
#define CI_SMEM (3 * BUF)                // 92160 B

__global__ __launch_bounds__(256, 2)
void convimma_kernel(const unsigned short* __restrict__ inq,
                     const signed char* __restrict__ wh,
                     const signed char* __restrict__ wl,
                     float* __restrict__ out,
                     int Cin, int Cout, int OD, int OH, int OW,
                     int IDp, int IHp, int IWp,
                     int kPerSplit, int sliceElems, int iaIdx, int ibIdx)
{
    extern __shared__ unsigned char dsm[];
    const uint32_t smb = smem_u32(dsm);

    const int t    = threadIdx.x;
    const int lane = t & 31;
    const int wid  = t >> 5;              // 0..7
    const int mw   = (wid & 3) * 32;      // warp M offset
    const int nww  = (wid >> 2) * 32;     // warp N offset (0 or 32)

    const int OHW  = OH * OW;
    const int ODHW = OD * OHW;
    const int IHWp = IHp * IWp;
    const int IWp2 = IWp >> 1;
    const int K    = Cin * 64;

    const int mBase = blockIdx.x * 128;
    const int cBase = blockIdx.y * 64;
    const int kBase = blockIdx.z * kPerSplit;

    // ---- A loader: thread = (row lm, kd-pair khalf); 32 k-elems ----
    const int lm    = t >> 1;             // 0..127
    const int khalf = t & 1;              // kd in {2*khalf, 2*khalf+1}
    const int mload = mBase + lm;
    const int n_l = mload / ODHW;
    int srem = mload % ODHW;
    const int od = srem / OHW; srem %= OHW;
    const int oh = srem / OW;
    const int ow = srem % OW;

    const int rowElem0 = (oh * 2) * IWp + 2 * ow;      // even
    const uint32_t aOff = (uint32_t)(lm * ROWB + khalf * 32);

    // ---- B loader: thread -> 32B (2 cp.async); 64 rows x 64B x 2 planes ----
    const int brow = t & 63;
    const int bpl  = (t >> 6) & 1;        // 0 = hi, 1 = lo
    const int bh2  = (t >> 7) & 1;        // which 32B half of the 64B row
    const signed char* wsrc = (bpl ? wl : wh) + (size_t)(cBase + brow) * K
                            + kBase + bh2 * 32;
    const uint32_t bDst = (uint32_t)(2 * TILE_A + bpl * TILE_B
                                     + brow * ROWB + bh2 * 32);

    const uint32_t lrow = (lane & 15);
    const uint32_t lsel = (lane >> 4) * 16;

    int acc_hh[2][4][4], acc_md[2][4][4];
#pragma unroll
    for (int a = 0; a < 2; ++a)
#pragma unroll
        for (int b = 0; b < 4; ++b)
#pragma unroll
            for (int q = 0; q < 4; ++q) { acc_hh[a][b][q] = 0; acc_md[a][b][q] = 0; }

    const int nCh = kPerSplit >> 6;

    unsigned wA[16];
    auto gatherA = [&](int kc) {
        const int cin = (kBase >> 6) + kc;
#pragma unroll
        for (int j = 0; j < 2; ++j) {
            const int kd  = 2 * khalf + j;
            const int idp = od * 2 + kd;
            const unsigned* p = (const unsigned*)(inq
                + ((size_t)(n_l * Cin + cin) * IDp + idp) * IHWp + rowElem0);
#pragma unroll
            for (int kh = 0; kh < 4; ++kh) {
                wA[j * 8 + 2 * kh]     = p[kh * IWp2];
                wA[j * 8 + 2 * kh + 1] = p[kh * IWp2 + 1];
            }
        }
    };

    auto cpasyncB = [&](int kc, int buf) {
        const uint32_t d = smb + buf * BUF + bDst;
        const signed char* s = wsrc + ((size_t)kc << 6);
        cpa16(d, s);
        cpa16(d + 16, s + 16);
        CP_COMMIT();
    };

    auto storeA = [&](int buf) {
        unsigned char* base = dsm + buf * BUF + aOff;
#pragma unroll
        for (int j = 0; j < 2; ++j) {
            uint4 hi, lo;
            hi.x = __byte_perm(wA[j * 8 + 0], wA[j * 8 + 1], 0x7531);
            lo.x = __byte_perm(wA[j * 8 + 0], wA[j * 8 + 1], 0x6420);
            hi.y = __byte_perm(wA[j * 8 + 2], wA[j * 8 + 3], 0x7531);
            lo.y = __byte_perm(wA[j * 8 + 2], wA[j * 8 + 3], 0x6420);
            hi.z = __byte_perm(wA[j * 8 + 4], wA[j * 8 + 5], 0x7531);
            lo.z = __byte_perm(wA[j * 8 + 4], wA[j * 8 + 5], 0x6420);
            hi.w = __byte_perm(wA[j * 8 + 6], wA[j * 8 + 7], 0x7531);
            lo.w = __byte_perm(wA[j * 8 + 6], wA[j * 8 + 7], 0x6420);
            *(uint4*)(base + j * 16)          = hi;
            *(uint4*)(base + TILE_A + j * 16) = lo;
        }
    };

    gatherA(0);
    cpasyncB(0, 0);
    storeA(0);
    gatherA(1);
    cpasyncB(1, 1);
    storeA(1);

    for (int kc = 0; kc < nCh; ++kc) {
        const int pf = kc + 2;

        if (kc + 1 < nCh)
            asm volatile("cp.async.wait_group 1;" ::: "memory");
        else
            asm volatile("cp.async.wait_group 0;" ::: "memory");
        __syncthreads();

        if (pf < nCh) { cpasyncB(pf, pf % 3); gatherA(pf); }

        const uint32_t aH = smb + (kc % 3) * BUF;
        const uint32_t aL = aH + TILE_A;
        const uint32_t bH = aH + 2 * TILE_A;
        const uint32_t bL = bH + TILE_B;

#pragma unroll
        for (int ks = 0; ks < 2; ++ks) {
            const uint32_t sel = lsel + ks * 32;
            uint32_t ah[2][4], al[2][4], bh[2][4], bl[2][4];
#pragma unroll
            for (int tm = 0; tm < 2; ++tm) {
                const uint32_t ro = (uint32_t)(mw + tm * 16 + lrow) * ROWB + sel;
                ldsm4(ah[tm], aH + ro);
                ldsm4(al[tm], aL + ro);
            }
#pragma unroll
            for (int bt = 0; bt < 2; ++bt) {
                const uint32_t ro = (uint32_t)(nww + bt * 16 + lrow) * ROWB + sel;
                ldsm4(bh[bt], bH + ro);
                ldsm4(bl[bt], bL + ro);
            }
#pragma unroll
            for (int tm = 0; tm < 2; ++tm)
#pragma unroll
                for (int bt = 0; bt < 2; ++bt)
#pragma unroll
                    for (int sub = 0; sub < 2; ++sub) {
                        const int tn = bt * 2 + sub;
                        imma(acc_hh[tm][tn], ah[tm], bh[bt][sub], bh[bt][sub + 2]);
                        imma(acc_md[tm][tn], ah[tm], bl[bt][sub], bl[bt][sub + 2]);
                        imma(acc_md[tm][tn], al[tm], bh[bt][sub], bh[bt][sub + 2]);
                    }
        }

        if (pf < nCh) storeA(pf % 3);
    }

    // ---- epilogue ----
    const float amA = __int_as_float(g_amax[iaIdx]);
    const float amB = __int_as_float(g_amax[ibIdx]);
    const float sAB = (amA / QMAX) * (amB / QMAX);

    float* outz = out + (size_t)blockIdx.z * sliceElems;
#pragma unroll
    for (int tm = 0; tm < 2; ++tm) {
#pragma unroll
        for (int half = 0; half < 2; ++half) {
            const int m   = mBase + mw + tm * 16 + (lane >> 2) + 8 * half;
            const int n_o = m / ODHW;
            const int s_o = m % ODHW;
            float* ob = outz + (size_t)(n_o * Cout + cBase) * ODHW + s_o;
#pragma unroll
            for (int tn = 0; tn < 4; ++tn) {
                const int col = nww + tn * 8 + 2 * (lane & 3);
                const float v0 = sAB * fmaf(65536.f,
                    (float)acc_hh[tm][tn][half * 2 + 0],
                    256.f * (float)acc_md[tm][tn][half * 2 + 0]);
                const float v1 = sAB * fmaf(65536.f,
                    (float)acc_hh[tm][tn][half * 2 + 1],
                    256.f * (float)acc_md[tm][tn][half * 2 + 1]);
                ob[(size_t)col * ODHW]       = v0;
                ob[(size_t)(col + 1) * ODHW] = v1;
            }
        }
    }
}

// ---------------------------------------------------------------------------
// BatchNorm stats, single pass over a non-split tensor (+ activated amax).
// ---------------------------------------------------------------------------
__global__ void bn_stats_kernel(const float* __restrict__ in,
                                const float* __restrict__ g,
                                const float* __restrict__ b,
                                int C, int ODHW, int amaxIdx)
{
    const int c = blockIdx.x;
    const int t = threadIdx.x;
    double s = 0.0, s2 = 0.0;
    float mn = 3.0e38f, mx = -3.0e38f;
    for (int n = 0; n < 32; ++n) {
        const float* base = in + (size_t)(n * C + c) * ODHW;
        for (int sp = t; sp < ODHW; sp += 256) {
            const float f = base[sp];
            const double v = (double)f;
            s += v; s2 += v * v;
            mn = fminf(mn, f); mx = fmaxf(mx, f);
        }
    }
    __shared__ double sh[256], sh2[256];
    __shared__ float smn[256], smx[256];
    sh[t] = s; sh2[t] = s2; smn[t] = mn; smx[t] = mx;
    __syncthreads();
    for (int o = 128; o > 0; o >>= 1) {
        if (t < o) {
            sh[t] += sh[t + o]; sh2[t] += sh2[t + o];
            smn[t] = fminf(smn[t], smn[t + o]);
            smx[t] = fmaxf(smx[t], smx[t + o]);
        }
        __syncthreads();
    }
    if (t == 0) {
        const double cnt  = 32.0 * (double)ODHW;
        const double mean = sh[0] / cnt;
        const double var  = sh2[0] / cnt - mean * mean;
        const double scd  = (double)g[c] / sqrt(var + 1e-5);
        const float sc = (float)scd;
        const float shv = (float)((double)b[c] - mean * scd);
        g_bnscale[c] = sc;
        g_bnshift[c] = shv;
        if (amaxIdx >= 0) {
            float a1 = smx[0] * sc + shv; a1 = (a1 >= 0.f) ? a1 : 0.2f * a1;
            float a2 = smn[0] * sc + shv; a2 = (a2 >= 0.f) ? a2 : 0.2f * a2;
            amax_atomic(amaxIdx, fmaxf(fabsf(a1), fabsf(a2)));
        }
    }
}

// ---------------------------------------------------------------------------
// Fused split-K reduction + BatchNorm stats (small tensors: conv3/conv4).
// ---------------------------------------------------------------------------
__global__ void bnstats_red_kernel(const float* __restrict__ partials,
                                   float* __restrict__ outbuf,
                                   const float* __restrict__ g,
                                   const float* __restrict__ b,
                                   int C, int ODHW, int nSlices, int sliceElems,
                                   int amaxIdx)
{
    const int c = blockIdx.x;
    const int t = threadIdx.x;
    double s = 0.0, s2 = 0.0;
    float mn = 3.0e38f, mx = -3.0e38f;
    for (int n = 0; n < 32; ++n) {
        const size_t base = ((size_t)n * C + c) * ODHW;
        for (int sp = t; sp < ODHW; sp += 256) {
            const size_t off = base + sp;
            float f = partials[off];
            for (int z = 1; z < nSlices; ++z)
                f += partials[off + (size_t)z * sliceElems];
            outbuf[off] = f;
            const double v = (double)f;
            s += v; s2 += v * v;
            mn = fminf(mn, f); mx = fmaxf(mx, f);
        }
    }
    __shared__ double sh[256], sh2[256];
    __shared__ float smn[256], smx[256];
    sh[t] = s; sh2[t] = s2; smn[t] = mn; smx[t] = mx;
    __syncthreads();
    for (int o = 128; o > 0; o >>= 1) {
        if (t < o) {
            sh[t] += sh[t + o]; sh2[t] += sh2[t + o];
            smn[t] = fminf(smn[t], smn[t + o]);
            smx[t] = fmaxf(smx[t], smx[t + o]);
        }
        __syncthreads();
    }
    if (t == 0) {
        const double cnt  = 32.0 * (double)ODHW;
        const double mean = sh[0] / cnt;
        const double var  = sh2[0] / cnt - mean * mean;
        const double scd  = (double)g[c] / sqrt(var + 1e-5);
        const float sc = (float)scd;
        const float shv = (float)((double)b[c] - mean * scd);
        g_bnscale[c] = sc;
        g_bnshift[c] = shv;
        if (amaxIdx >= 0) {
            float a1 = smx[0] * sc + shv; a1 = (a1 >= 0.f) ? a1 : 0.2f * a1;
            float a2 = smn[0] * sc + shv; a2 = (a2 >= 0.f) ? a2 : 0.2f * a2;
            amax_atomic(amaxIdx, fmaxf(fabsf(a1), fabsf(a2)));
        }
    }
}

// ---------------------------------------------------------------------------
// BN apply + lrelu in place (fp32, conv4 output).
// ---------------------------------------------------------------------------
__global__ void bn_lrelu_kernel(float4* __restrict__ x, int C, int ODHW4, int total4)
{
    const int i = blockIdx.x * 256 + threadIdx.x;
    if (i >= total4) return;
    const int c = (i / ODHW4) % C;
    const float sc = g_bnscale[c], sh = g_bnshift[c];
    float4 v = x[i];
    v.x = v.x * sc + sh; v.x = (v.x >= 0.f) ? v.x : 0.2f * v.x;
    v.y = v.y * sc + sh; v.y = (v.y >= 0.f) ? v.y : 0.2f * v.y;
    v.z = v.z * sc + sh; v.z = (v.z >= 0.f) ? v.z : 0.2f * v.z;
    v.w = v.w * sc + sh; v.w = (v.w >= 0.f) ? v.w : 0.2f * v.w;
    x[i] = v;
}

// ---------------------------------------------------------------------------
// Minibatch discrimination + final reduction.
// ---------------------------------------------------------------------------
__global__ void pairwise_kernel()
{
    const int i = blockIdx.y, j = blockIdx.x, t = threadIdx.x;
    const float* a = g_c4 + (size_t)i * 16384;
    const float* b = g_c4 + (size_t)j * 16384;
    float s = 0.f;
    for (int k = t; k < 16384; k += 256) s += fabsf(a[k] - b[k]);
    __shared__ float sh[256];
    sh[t] = s;
    __syncthreads();
    for (int o = 128; o > 0; o >>= 1) {
        if (t < o) sh[t] += sh[t + o];
        __syncthreads();
    }
    if (t == 0)
        g_d[i * 32 + j] = sh[0] * (1.f / 16384.f) + ((i == j) ? 1e6f : 0.f);
}

__global__ void final_kernel(const float* __restrict__ w5, float* __restrict__ out)
{
    const int n = blockIdx.x, t = threadIdx.x;

    __shared__ float shm[256];
    shm[t] = (t < 32) ? g_d[n * 32 + t] : 1e30f;
    __syncthreads();
    for (int o = 128; o > 0; o >>= 1) {
        if (t < o) shm[t] = fminf(shm[t], shm[t + o]);
        __syncthreads();
    }
    const float s = shm[0];
    __syncthreads();

    double acc = 0.0;
    const float* h = g_c4 + (size_t)n * 16384;
    for (int k = t; k < 16384; k += 256)
        acc += (double)h[k] * (double)w5[k];
    if (t < 32)
        acc += (double)s * (double)w5[16384 + t];

    __shared__ double shd[256];
    shd[t] = acc;
    __syncthreads();
    for (int o = 128; o > 0; o >>= 1) {
        if (t < o) shd[t] += shd[t + o];
        __syncthreads();
    }
    if (t == 0) out[n] = (float)shd[0];
}

// ---------------------------------------------------------------------------
// Launch chain. Inputs: x, w1, w2, g2, b2, w3, g3, b3, w4, g4, b4, w5
// ---------------------------------------------------------------------------
extern "C" void kernel_launch(void* const* d_in, const int* in_sizes, int n_in,
                              void* d_out, int out_size)
{
    (void)in_sizes; (void)n_in; (void)out_size;
    const float* x  = (const float*)d_in[0];
    const float* w1 = (const float*)d_in[1];
    const float* w2 = (const float*)d_in[2];
    const float* g2 = (const float*)d_in[3];
    const float* b2 = (const float*)d_in[4];
    const float* w3 = (const float*)d_in[5];
    const float* g3 = (const float*)d_in[6];
    const float* b3 = (const float*)d_in[7];
    const float* w4 = (const float*)d_in[8];
    const float* g4 = (const float*)d_in[9];
    const float* b4 = (const float*)d_in[10];
    const float* w5 = (const float*)d_in[11];
    float* out = (float*)d_out;

    float *h1, *c2, *c3, *c3p, *c4, *c4p;
    unsigned short *h1q, *c2q, *c3q;
    signed char *w2h, *w2l, *w3h, *w3l, *w4h, *w4l;
    cudaGetSymbolAddress((void**)&h1,  g_h1);
    cudaGetSymbolAddress((void**)&h1q, g_h1q);
    cudaGetSymbolAddress((void**)&c2,  g_c2);
    cudaGetSymbolAddress((void**)&c2q, g_c2q);
    cudaGetSymbolAddress((void**)&c3,  g_c3);
    cudaGetSymbolAddress((void**)&c3p, g_c3p);
    cudaGetSymbolAddress((void**)&c3q, g_c3q);
    cudaGetSymbolAddress((void**)&c4,  g_c4);
    cudaGetSymbolAddress((void**)&c4p, g_c4p);
    cudaGetSymbolAddress((void**)&w2h, g_w2h);
    cudaGetSymbolAddress((void**)&w2l, g_w2l);
    cudaGetSymbolAddress((void**)&w3h, g_w3h);
    cudaGetSymbolAddress((void**)&w3l, g_w3l);
    cudaGetSymbolAddress((void**)&w4h, g_w4h);
    cudaGetSymbolAddress((void**)&w4l, g_w4l);

    cudaFuncSetAttribute(convimma_kernel,
                         cudaFuncAttributeMaxDynamicSharedMemorySize, CI_SMEM);

    // amax init + fused weight amax/quant
    zeroamax_kernel<<<1, 32>>>();
    wamax3_kernel<<<dim3(256, 3), 256>>>((const float4*)w2, (const float4*)w3,
                                         (const float4*)w4);
    wquant3_kernel<<<dim3(4096, 3), 256>>>(w2, w3, w4,
                                           w2h, w2l, w3h, w3l, w4h, w4l);

    // L1 + padded quantize (h1: 16,32,32 -> 18,34,34; IWp2=17)
    conv1_kernel<<<dim3(16, 32), 1024>>>(x, w1);
    quantA_pad_kernel<<<dim3(3, 18, 2048), 256>>>(h1, (unsigned*)h1q,
        16, 32, 32, 18, 34, 17, 0);

    // L2: M=65536, N=128 (2 n-tiles), K=4096
    convimma_kernel<<<dim3(512, 2, 1), 256, CI_SMEM>>>(h1q, w2h, w2l, c2,
        64, 128, 8, 16, 16, 18, 34, 34, 4096, 0, 0, 1);
    bn_stats_kernel<<<128, 256>>>(c2, g2, b2, 128, 2048, 2);
    quantBN_pad_kernel<<<dim3(1, 10, 4096), 256>>>(c2, (unsigned*)c2q,
        127, 8, 16, 16, 10, 18, 9, 2);

    // L3: M=8192, N=256 (4 n-tiles), K=8192, split-K=2; fused reduce+stats
    convimma_kernel<<<dim3(64, 4, 2), 256, CI_SMEM>>>(c2q, w3h, w3l, c3p,
        128, 256, 4, 8, 8, 10, 18, 18, 4096, 2097152, 2, 3);
    bnstats_red_kernel<<<256, 256>>>(c3p, c3, g3, b3, 256, 256, 2, 2097152, 4);
    quantBN_pad_kernel<<<dim3(1, 6, 8192), 256>>>(c3, (unsigned*)c3q,
        255, 4, 8, 8, 6, 10, 5, 4);

    // L4: M=1024, N=512 (8 n-tiles), K=16384, split-K=8; fused reduce+stats
    convimma_kernel<<<dim3(8, 8, 8), 256, CI_SMEM>>>(c3q, w4h, w4l, c4p,
        256, 512, 2, 4, 4, 6, 10, 10, 2048, 524288, 4, 5);
    bnstats_red_kernel<<<512, 256>>>(c4p, c4, g4, b4, 512, 32, 8, 524288, -1);
    bn_lrelu_kernel<<<131072 / 256, 256>>>((float4*)c4, 512, 8, 131072);

    // minibatch discrimination + final
    pairwise_kernel<<<dim3(32, 32), 256>>>();
    final_kernel<<<32, 256>>>(w5, out);
}

// round 17
// speedup vs baseline: 1.1090x; 1.0185x over previous
#include <cuda_runtime.h>
#include <cstdint>

#define DEVFN __device__ __forceinline__

// ---------------------------------------------------------------------------
// Scratch (static device globals — no allocations anywhere)
// Quantized activations stored HALO-PADDED: (IDp=ID+2, IHp=IH+2, IWp=IW+2
// rounded even), left-pad 1, halo = 0 (conv zero-padding materialized).
// Halo words are NEVER written after init: __device__ globals are
// zero-initialized, interior writes never touch halo -> quantizers skip
// full-halo rows (deterministic across graph replays).
// ---------------------------------------------------------------------------
__device__ float          g_h1 [33554432u];            // conv1 out fp32
__device__ unsigned short g_h1q[42614784u];            // 32*64*18*34*34
__device__ float          g_c2 [8388608u];
__device__ unsigned short g_c2q[13271040u];            // 32*128*10*18*18
__device__ float          g_c3 [2097152u];
__device__ float          g_c3p[2u * 2097152u];
__device__ unsigned short g_c3q[4915200u];             // 32*256*6*10*10
__device__ float          g_c4 [524288u];
__device__ float          g_c4p[8u * 524288u];
__device__ signed char    g_w2h[524288u],  g_w2l[524288u];
__device__ signed char    g_w3h[2097152u], g_w3l[2097152u];
__device__ signed char    g_w4h[8388608u], g_w4l[8388608u];
__device__ int            g_amax[8];                   // float bits, >= 0
__device__ float          g_bnscale[512];
__device__ float          g_bnshift[512];
__device__ float          g_d[32 * 32];

#define QMAX 32512.0f

// ---------------------------------------------------------------------------
// Helpers
// ---------------------------------------------------------------------------
DEVFN uint32_t smem_u32(const void* p)
{
    uint32_t a;
    asm("{ .reg .u64 t; cvta.to.shared.u64 t, %1; cvt.u32.u64 %0, t; }"
        : "=r"(a) : "l"(p));
    return a;
}

DEVFN void ldsm4(uint32_t* r, uint32_t addr)
{
    asm volatile("ldmatrix.sync.aligned.m8n8.x4.shared.b16 {%0,%1,%2,%3}, [%4];"
                 : "=r"(r[0]), "=r"(r[1]), "=r"(r[2]), "=r"(r[3]) : "r"(addr));
}

DEVFN void imma(int* c, const uint32_t* a, uint32_t b0, uint32_t b1)
{
    asm volatile(
        "mma.sync.aligned.m16n8k32.row.col.s32.s8.s8.s32 "
        "{%0,%1,%2,%3}, {%4,%5,%6,%7}, {%8,%9}, {%0,%1,%2,%3};"
        : "+r"(c[0]), "+r"(c[1]), "+r"(c[2]), "+r"(c[3])
        : "r"(a[0]), "r"(a[1]), "r"(a[2]), "r"(a[3]), "r"(b0), "r"(b1));
}

DEVFN void cpa16(uint32_t dst, const void* src)
{
    asm volatile("cp.async.cg.shared.global [%0], [%1], 16;"
                 :: "r"(dst), "l"(src) : "memory");
}
#define CP_COMMIT() asm volatile("cp.async.commit_group;" ::: "memory")

DEVFN void amax_atomic(int idx, float v)
{
    atomicMax(&g_amax[idx], __float_as_int(v));
}

DEVFN unsigned short quant16(float v, float inv)
{
    float q = rintf(v * inv);
    q = fminf(fmaxf(q, -QMAX), QMAX);
    const int Q = (int)q;
    const int h = (Q + 128) >> 8;          // h in [-127,127]
    const int l = Q - (h << 8);            // l in [-128,127]
    return (unsigned short)(((h & 0xff) << 8) | (l & 0xff));
}

// ---------------------------------------------------------------------------
// Setup kernels (fused across the 3 weight tensors)
// ---------------------------------------------------------------------------
__global__ void zeroamax_kernel()
{
    if (threadIdx.x < 8) g_amax[threadIdx.x] = 0;
}

__global__ void wamax3_kernel(const float4* __restrict__ w2,
                              const float4* __restrict__ w3,
                              const float4* __restrict__ w4)
{
    const int which = blockIdx.y;
    const float4* w = (which == 0) ? w2 : (which == 1) ? w3 : w4;
    const int n4    = (which == 0) ? 131072 : (which == 1) ? 524288 : 2097152;
    const int idx   = (which == 0) ? 1 : (which == 1) ? 3 : 5;

    const int stride = gridDim.x * 256;
    float am = 0.f;
    for (int i = blockIdx.x * 256 + threadIdx.x; i < n4; i += stride) {
        const float4 v = w[i];
        am = fmaxf(am, fmaxf(fmaxf(fabsf(v.x), fabsf(v.y)),
                             fmaxf(fabsf(v.z), fabsf(v.w))));
    }
    __shared__ float sh[256];
    sh[threadIdx.x] = am;
    __syncthreads();
    for (int o = 128; o > 0; o >>= 1) {
        if (threadIdx.x < o) sh[threadIdx.x] = fmaxf(sh[threadIdx.x], sh[threadIdx.x + o]);
        __syncthreads();
    }
    if (threadIdx.x == 0) amax_atomic(idx, sh[0]);
}

__global__ void wquant3_kernel(const float* __restrict__ w2,
                               const float* __restrict__ w3,
                               const float* __restrict__ w4,
                               signed char* __restrict__ o2h, signed char* __restrict__ o2l,
                               signed char* __restrict__ o3h, signed char* __restrict__ o3l,
                               signed char* __restrict__ o4h, signed char* __restrict__ o4l)
{
    const int which = blockIdx.y;
    const float* w = (which == 0) ? w2 : (which == 1) ? w3 : w4;
    signed char* oh = (which == 0) ? o2h : (which == 1) ? o3h : o4h;
    signed char* ol = (which == 0) ? o2l : (which == 1) ? o3l : o4l;
    const int n   = (which == 0) ? 524288 : (which == 1) ? 2097152 : 8388608;
    const int idx = (which == 0) ? 1 : (which == 1) ? 3 : 5;

    const float amax = __int_as_float(g_amax[idx]);
    const float inv = QMAX / fmaxf(amax, 1e-30f);
    const int stride = gridDim.x * 256;
    for (int i = blockIdx.x * 256 + threadIdx.x; i < n; i += stride) {
        const unsigned short q = quant16(w[i], inv);
        oh[i] = (signed char)(q >> 8);
        ol[i] = (signed char)(q & 0xff);
    }
}

// ---------------------------------------------------------------------------
// Padded quantizers, FLAT-indexed (thread -> one u32 = 2 elements).
// Full-halo rows are SKIPPED (zero-init + never overwritten).
// ---------------------------------------------------------------------------
__global__ void quantA_pad_kernel(const float* __restrict__ in,
                                  unsigned* __restrict__ out,
                                  int ID, int IH, int IW,
                                  int IDp, int IHp, int IWp2, int amaxIdx)
{
    const int hw = blockIdx.x * 256 + threadIdx.x;
    const int HW = IHp * IWp2;
    if (hw >= HW) return;
    const int hp = hw / IWp2;
    const int w2 = hw - hp * IWp2;
    const int dp = blockIdx.y;
    const int z  = blockIdx.z;

    if (dp < 1 || dp > ID || hp < 1 || hp > IH) return;   // halo stays zero

    const float amax = __int_as_float(g_amax[amaxIdx]);
    const float inv = QMAX / fmaxf(amax, 1e-30f);

    float v0 = 0.f, v1 = 0.f;
    const size_t srcrow = (((size_t)z * ID + (dp - 1)) * IH + (hp - 1)) * IW;
    const int wp0 = 2 * w2;
    if (wp0 >= 1 && wp0 <= IW) v0 = in[srcrow + wp0 - 1];
    if (wp0 + 1 <= IW)         v1 = in[srcrow + wp0];
    out[((size_t)z * IDp + dp) * HW + hw] =
        (unsigned)quant16(v0, inv) | ((unsigned)quant16(v1, inv) << 16);
}

__global__ void quantBN_pad_kernel(const float* __restrict__ in,
                                   unsigned* __restrict__ out,
                                   int Cmask, int ID, int IH, int IW,
                                   int IDp, int IHp, int IWp2, int amaxIdx)
{
    const int hw = blockIdx.x * 256 + threadIdx.x;
    const int HW = IHp * IWp2;
    if (hw >= HW) return;
    const int hp = hw / IWp2;
    const int w2 = hw - hp * IWp2;
    const int dp = blockIdx.y;
    const int z  = blockIdx.z;
    const int c  = z & Cmask;

    if (dp < 1 || dp > ID || hp < 1 || hp > IH) return;   // halo stays zero

    const float sc = g_bnscale[c], sh = g_bnshift[c];
    const float amax = __int_as_float(g_amax[amaxIdx]);
    const float inv = QMAX / fmaxf(amax, 1e-30f);

    float v0 = 0.f, v1 = 0.f;
    const size_t srcrow = (((size_t)z * ID + (dp - 1)) * IH + (hp - 1)) * IW;
    const int wp0 = 2 * w2;
    if (wp0 >= 1 && wp0 <= IW) {
        float v = in[srcrow + wp0 - 1] * sc + sh;
        v0 = (v >= 0.f) ? v : 0.2f * v;
    }
    if (wp0 + 1 <= IW) {
        float v = in[srcrow + wp0] * sc + sh;
        v1 = (v >= 0.f) ? v : 0.2f * v;
    }
    out[((size_t)z * IDp + dp) * HW + hw] =
        (unsigned)quant16(v0, inv) | ((unsigned)quant16(v1, inv) << 16);
}

// ---------------------------------------------------------------------------
// Layer 1: conv3d (64,1,2,4,4), stride (2,2,2), pad (0,1,1), fused lrelu.
// 512-thread blocks (z = oh half) -> 2 CTAs/SM for scoreboard-stall cover.
// ---------------------------------------------------------------------------
__global__ __launch_bounds__(512, 2)
void conv1_kernel(const float* __restrict__ x, const float* __restrict__ w1)
{
    __shared__ float ws[2048];
    __shared__ float sm[512];
    const int t = threadIdx.x;
    for (int i = t; i < 2048; i += 512) ws[i] = w1[i];
    __syncthreads();

    const int od = blockIdx.x;
    const int n  = blockIdx.y;
    const int oh = blockIdx.z * 16 + (t >> 5);
    const int ow = t & 31;

    const float* xb = x + (size_t)n * 131072 + (size_t)(od * 2) * 4096;
    const int ih0 = oh * 2 - 1;
    const int iw0 = ow * 2 - 1;

    float v[32];
#pragma unroll
    for (int kd = 0; kd < 2; ++kd)
#pragma unroll
        for (int kh = 0; kh < 4; ++kh)
#pragma unroll
            for (int kw = 0; kw < 4; ++kw) {
                const int ih = ih0 + kh, iw = iw0 + kw;
                const bool ok = ((unsigned)ih < 64u) && ((unsigned)iw < 64u);
                v[kd * 16 + kh * 4 + kw] = ok ? xb[kd * 4096 + ih * 64 + iw] : 0.f;
            }

    float* outb = g_h1 + ((size_t)(n * 64) * 16 + od) * 1024 + oh * 32 + ow;
    float am = 0.f;
#pragma unroll 4
    for (int c = 0; c < 64; ++c) {
        const float4* wp = (const float4*)&ws[c * 32];
        float acc = 0.f;
#pragma unroll
        for (int q = 0; q < 8; ++q) {
            const float4 w4 = wp[q];
            acc += v[q * 4 + 0] * w4.x + v[q * 4 + 1] * w4.y
                 + v[q * 4 + 2] * w4.z + v[q * 4 + 3] * w4.w;
        }
        acc = (acc >= 0.f) ? acc : 0.2f * acc;
        am = fmaxf(am, fabsf(acc));
        outb[(size_t)c * 16384] = acc;
    }

    sm[t] = am;
    __syncthreads();
    for (int o = 256; o > 0; o >>= 1) {
        if (t < o) sm[t] = fmaxf(sm[t], sm[t + o]);
        __syncthreads();
    }
    if (t == 0) amax_atomic(0, sm[0]);
}

// ---------------------------------------------------------------------------
// int8 IMMA implicit-GEMM conv3d, HALO-PADDED input, K-CHUNK 64.
// CTA 128x64, 256 threads (8 warps, 4x2), warp tile 32x32; 2 CTAs/SM.
// 3-stage pipeline, one barrier per chunk (CUTLASS ordering).
// ---------------------------------------------------------------------------
#define ROWB   80
#define TILE_A (128 * ROWB)              // 10240 B
#define TILE_B (64 * ROWB)               //  5120 B
#define BUF    (2 * TILE_A + 2 * TILE_B) // 30720 B: Ah, Al, Bh, Bl
#define CI_SMEM (3 * BUF)                // 92160 B

__global__ __launch_bounds__(256, 2)
void convimma_kernel(const unsigned short* __restrict__ inq,
                     const signed char* __restrict__ wh,
                     const signed char* __restrict__ wl,
                     float* __restrict__ out,
                     int Cin, int Cout, int OD, int OH, int OW,
                     int IDp, int IHp, int IWp,
                     int kPerSplit, int sliceElems, int iaIdx, int ibIdx)
{
    extern __shared__ unsigned char dsm[];
    const uint32_t smb = smem_u32(dsm);

    const int t    = threadIdx.x;
    const int lane = t & 31;
    const int wid  = t >> 5;
    const int mw   = (wid & 3) * 32;
    const int nww  = (wid >> 2) * 32;

    const int OHW  = OH * OW;
    const int ODHW = OD * OHW;
    const int IHWp = IHp * IWp;
    const int IWp2 = IWp >> 1;
    const int K    = Cin * 64;

    const int mBase = blockIdx.x * 128;
    const int cBase = blockIdx.y * 64;
    const int kBase = blockIdx.z * kPerSplit;

    const int lm    = t >> 1;
    const int khalf = t & 1;
    const int mload = mBase + lm;
    const int n_l = mload / ODHW;
    int srem = mload % ODHW;
    const int od = srem / OHW; srem %= OHW;
    const int oh = srem / OW;
    const int ow = srem % OW;

    const int rowElem0 = (oh * 2) * IWp + 2 * ow;
    const uint32_t aOff = (uint32_t)(lm * ROWB + khalf * 32);

    const int brow = t & 63;
    const int bpl  = (t >> 6) & 1;
    const int bh2  = (t >> 7) & 1;
    const signed char* wsrc = (bpl ? wl : wh) + (size_t)(cBase + brow) * K
                            + kBase + bh2 * 32;
    const uint32_t bDst = (uint32_t)(2 * TILE_A + bpl * TILE_B
                                     + brow * ROWB + bh2 * 32);

    const uint32_t lrow = (lane & 15);
    const uint32_t lsel = (lane >> 4) * 16;

    int acc_hh[2][4][4], acc_md[2][4][4];
#pragma unroll
    for (int a = 0; a < 2; ++a)
#pragma unroll
        for (int b = 0; b < 4; ++b)
#pragma unroll
            for (int q = 0; q < 4; ++q) { acc_hh[a][b][q] = 0; acc_md[a][b][q] = 0; }

    const int nCh = kPerSplit >> 6;

    unsigned wA[16];
    auto gatherA = [&](int kc) {
        const int cin = (kBase >> 6) + kc;
#pragma unroll
        for (int j = 0; j < 2; ++j) {
            const int kd  = 2 * khalf + j;
            const int idp = od * 2 + kd;
            const unsigned* p = (const unsigned*)(inq
                + ((size_t)(n_l * Cin + cin) * IDp + idp) * IHWp + rowElem0);
#pragma unroll
            for (int kh = 0; kh < 4; ++kh) {
                wA[j * 8 + 2 * kh]     = p[kh * IWp2];
                wA[j * 8 + 2 * kh + 1] = p[kh * IWp2 + 1];
            }
        }
    };

    auto cpasyncB = [&](int kc, int buf) {
        const uint32_t d = smb + buf * BUF + bDst;
        const signed char* s = wsrc + ((size_t)kc << 6);
        cpa16(d, s);
        cpa16(d + 16, s + 16);
        CP_COMMIT();
    };

    auto storeA = [&](int buf) {
        unsigned char* base = dsm + buf * BUF + aOff;
#pragma unroll
        for (int j = 0; j < 2; ++j) {
            uint4 hi, lo;
            hi.x = __byte_perm(wA[j * 8 + 0], wA[j * 8 + 1], 0x7531);
            lo.x = __byte_perm(wA[j * 8 + 0], wA[j * 8 + 1], 0x6420);
            hi.y = __byte_perm(wA[j * 8 + 2], wA[j * 8 + 3], 0x7531);
            lo.y = __byte_perm(wA[j * 8 + 2], wA[j * 8 + 3], 0x6420);
            hi.z = __byte_perm(wA[j * 8 + 4], wA[j * 8 + 5], 0x7531);
            lo.z = __byte_perm(wA[j * 8 + 4], wA[j * 8 + 5], 0x6420);
            hi.w = __byte_perm(wA[j * 8 + 6], wA[j * 8 + 7], 0x7531);
            lo.w = __byte_perm(wA[j * 8 + 6], wA[j * 8 + 7], 0x6420);
            *(uint4*)(base + j * 16)          = hi;
            *(uint4*)(base + TILE_A + j * 16) = lo;
        }
    };

    gatherA(0);
    cpasyncB(0, 0);
    storeA(0);
    gatherA(1);
    cpasyncB(1, 1);
    storeA(1);

    for (int kc = 0; kc < nCh; ++kc) {
        const int pf = kc + 2;

        if (kc + 1 < nCh)
            asm volatile("cp.async.wait_group 1;" ::: "memory");
        else
            asm volatile("cp.async.wait_group 0;" ::: "memory");
        __syncthreads();

        if (pf < nCh) { cpasyncB(pf, pf % 3); gatherA(pf); }

        const uint32_t aH = smb + (kc % 3) * BUF;
        const uint32_t aL = aH + TILE_A;
        const uint32_t bH = aH + 2 * TILE_A;
        const uint32_t bL = bH + TILE_B;

#pragma unroll
        for (int ks = 0; ks < 2; ++ks) {
            const uint32_t sel = lsel + ks * 32;
            uint32_t ah[2][4], al[2][4], bh[2][4], bl[2][4];
#pragma unroll
            for (int tm = 0; tm < 2; ++tm) {
                const uint32_t ro = (uint32_t)(mw + tm * 16 + lrow) * ROWB + sel;
                ldsm4(ah[tm], aH + ro);
                ldsm4(al[tm], aL + ro);
            }
#pragma unroll
            for (int bt = 0; bt < 2; ++bt) {
                const uint32_t ro = (uint32_t)(nww + bt * 16 + lrow) * ROWB + sel;
                ldsm4(bh[bt], bH + ro);
                ldsm4(bl[bt], bL + ro);
            }
#pragma unroll
            for (int tm = 0; tm < 2; ++tm)
#pragma unroll
                for (int bt = 0; bt < 2; ++bt)
#pragma unroll
                    for (int sub = 0; sub < 2; ++sub) {
                        const int tn = bt * 2 + sub;
                        imma(acc_hh[tm][tn], ah[tm], bh[bt][sub], bh[bt][sub + 2]);
                        imma(acc_md[tm][tn], ah[tm], bl[bt][sub], bl[bt][sub + 2]);
                        imma(acc_md[tm][tn], al[tm], bh[bt][sub], bh[bt][sub + 2]);
                    }
        }

        if (pf < nCh) storeA(pf % 3);
    }

    // ---- epilogue ----
    const float amA = __int_as_float(g_amax[iaIdx]);
    const float amB = __int_as_float(g_amax[ibIdx]);
    const float sAB = (amA / QMAX) * (amB / QMAX);

    float* outz = out + (size_t)blockIdx.z * sliceElems;
#pragma unroll
    for (int tm = 0; tm < 2; ++tm) {
#pragma unroll
        for (int half = 0; half < 2; ++half) {
            const int m   = mBase + mw + tm * 16 + (lane >> 2) + 8 * half;
            const int n_o = m / ODHW;
            const int s_o = m % ODHW;
            float* ob = outz + (size_t)(n_o * Cout + cBase) * ODHW + s_o;
#pragma unroll
            for (int tn = 0; tn < 4; ++tn) {
                const int col = nww + tn * 8 + 2 * (lane & 3);
                const float v0 = sAB * fmaf(65536.f,
                    (float)acc_hh[tm][tn][half * 2 + 0],
                    256.f * (float)acc_md[tm][tn][half * 2 + 0]);
                const float v1 = sAB * fmaf(65536.f,
                    (float)acc_hh[tm][tn][half * 2 + 1],
                    256.f * (float)acc_md[tm][tn][half * 2 + 1]);
                ob[(size_t)col * ODHW]       = v0;
                ob[(size_t)(col + 1) * ODHW] = v1;
            }
        }
    }
}

// ---------------------------------------------------------------------------
// BatchNorm stats, single pass over a non-split tensor (+ activated amax).
// ---------------------------------------------------------------------------
__global__ void bn_stats_kernel(const float* __restrict__ in,
                                const float* __restrict__ g,
                                const float* __restrict__ b,
                                int C, int ODHW, int amaxIdx)
{
    const int c = blockIdx.x;
    const int t = threadIdx.x;
    double s = 0.0, s2 = 0.0;
    float mn = 3.0e38f, mx = -3.0e38f;
    for (int n = 0; n < 32; ++n) {
        const float* base = in + (size_t)(n * C + c) * ODHW;
        for (int sp = t; sp < ODHW; sp += 256) {
            const float f = base[sp];
            const double v = (double)f;
            s += v; s2 += v * v;
            mn = fminf(mn, f); mx = fmaxf(mx, f);
        }
    }
    __shared__ double sh[256], sh2[256];
    __shared__ float smn[256], smx[256];
    sh[t] = s; sh2[t] = s2; smn[t] = mn; smx[t] = mx;
    __syncthreads();
    for (int o = 128; o > 0; o >>= 1) {
        if (t < o) {
            sh[t] += sh[t + o]; sh2[t] += sh2[t + o];
            smn[t] = fminf(smn[t], smn[t + o]);
            smx[t] = fmaxf(smx[t], smx[t + o]);
        }
        __syncthreads();
    }
    if (t == 0) {
        const double cnt  = 32.0 * (double)ODHW;
        const double mean = sh[0] / cnt;
        const double var  = sh2[0] / cnt - mean * mean;
        const double scd  = (double)g[c] / sqrt(var + 1e-5);
        const float sc = (float)scd;
        const float shv = (float)((double)b[c] - mean * scd);
        g_bnscale[c] = sc;
        g_bnshift[c] = shv;
        if (amaxIdx >= 0) {
            float a1 = smx[0] * sc + shv; a1 = (a1 >= 0.f) ? a1 : 0.2f * a1;
            float a2 = smn[0] * sc + shv; a2 = (a2 >= 0.f) ? a2 : 0.2f * a2;
            amax_atomic(amaxIdx, fmaxf(fabsf(a1), fabsf(a2)));
        }
    }
}

// ---------------------------------------------------------------------------
// Fused split-K reduction + BatchNorm stats (small tensors: conv3/conv4).
// ---------------------------------------------------------------------------
__global__ void bnstats_red_kernel(const float* __restrict__ partials,
                                   float* __restrict__ outbuf,
                                   const float* __restrict__ g,
                                   const float* __restrict__ b,
                                   int C, int ODHW, int nSlices, int sliceElems,
                                   int amaxIdx)
{
    const int c = blockIdx.x;
    const int t = threadIdx.x;
    double s = 0.0, s2 = 0.0;
    float mn = 3.0e38f, mx = -3.0e38f;
    for (int n = 0; n < 32; ++n) {
        const size_t base = ((size_t)n * C + c) * ODHW;
        for (int sp = t; sp < ODHW; sp += 256) {
            const size_t off = base + sp;
            float f = partials[off];
            for (int z = 1; z < nSlices; ++z)
                f += partials[off + (size_t)z * sliceElems];
            outbuf[off] = f;
            const double v = (double)f;
            s += v; s2 += v * v;
            mn = fminf(mn, f); mx = fmaxf(mx, f);
        }
    }
    __shared__ double sh[256], sh2[256];
    __shared__ float smn[256], smx[256];
    sh[t] = s; sh2[t] = s2; smn[t] = mn; smx[t] = mx;
    __syncthreads();
    for (int o = 128; o > 0; o >>= 1) {
        if (t < o) {
            sh[t] += sh[t + o]; sh2[t] += sh2[t + o];
            smn[t] = fminf(smn[t], smn[t + o]);
            smx[t] = fmaxf(smx[t], smx[t + o]);
        }
        __syncthreads();
    }
    if (t == 0) {
        const double cnt  = 32.0 * (double)ODHW;
        const double mean = sh[0] / cnt;
        const double var  = sh2[0] / cnt - mean * mean;
        const double scd  = (double)g[c] / sqrt(var + 1e-5);
        const float sc = (float)scd;
        const float shv = (float)((double)b[c] - mean * scd);
        g_bnscale[c] = sc;
        g_bnshift[c] = shv;
        if (amaxIdx >= 0) {
            float a1 = smx[0] * sc + shv; a1 = (a1 >= 0.f) ? a1 : 0.2f * a1;
            float a2 = smn[0] * sc + shv; a2 = (a2 >= 0.f) ? a2 : 0.2f * a2;
            amax_atomic(amaxIdx, fmaxf(fabsf(a1), fabsf(a2)));
        }
    }
}

// ---------------------------------------------------------------------------
// BN apply + lrelu in place (fp32, conv4 output).
// ---------------------------------------------------------------------------
__global__ void bn_lrelu_kernel(float4* __restrict__ x, int C, int ODHW4, int total4)
{
    const int i = blockIdx.x * 256 + threadIdx.x;
    if (i >= total4) return;
    const int c = (i / ODHW4) % C;
    const float sc = g_bnscale[c], sh = g_bnshift[c];
    float4 v = x[i];
    v.x = v.x * sc + sh; v.x = (v.x >= 0.f) ? v.x : 0.2f * v.x;
    v.y = v.y * sc + sh; v.y = (v.y >= 0.f) ? v.y : 0.2f * v.y;
    v.z = v.z * sc + sh; v.z = (v.z >= 0.f) ? v.z : 0.2f * v.z;
    v.w = v.w * sc + sh; v.w = (v.w >= 0.f) ? v.w : 0.2f * v.w;
    x[i] = v;
}

// ---------------------------------------------------------------------------
// Minibatch discrimination, tiled: block = (i, group of 8 j).
// Each thread keeps its 64-element slice of row i in registers and streams
// the 8 b rows (halves global/L2 traffic vs one block per (i,j)).
// Same per-(i,j) fp32 accumulation order as before -> bit-identical d.
// ---------------------------------------------------------------------------
__global__ __launch_bounds__(256, 4)
void pairwise_kernel()
{
    const int i  = blockIdx.x;
    const int jg = blockIdx.y * 8;
    const int t  = threadIdx.x;

    const float* a = g_c4 + (size_t)i * 16384;
    float av[64];
#pragma unroll
    for (int q = 0; q < 64; ++q) av[q] = a[t + q * 256];

    float s[8];
#pragma unroll
    for (int j = 0; j < 8; ++j) s[j] = 0.f;

#pragma unroll 2
    for (int j = 0; j < 8; ++j) {
        const float* b = g_c4 + (size_t)(jg + j) * 16384;
#pragma unroll
        for (int q = 0; q < 64; ++q)
            s[j] += fabsf(av[q] - b[t + q * 256]);
    }

    __shared__ float sh[256];
#pragma unroll
    for (int j = 0; j < 8; ++j) {
        sh[t] = s[j];
        __syncthreads();
        for (int o = 128; o > 0; o >>= 1) {
            if (t < o) sh[t] += sh[t + o];
            __syncthreads();
        }
        if (t == 0)
            g_d[i * 32 + jg + j] = sh[0] * (1.f / 16384.f)
                                 + ((i == jg + j) ? 1e6f : 0.f);
        __syncthreads();
    }
}

__global__ void final_kernel(const float* __restrict__ w5, float* __restrict__ out)
{
    const int n = blockIdx.x, t = threadIdx.x;

    __shared__ float shm[256];
    shm[t] = (t < 32) ? g_d[n * 32 + t] : 1e30f;
    __syncthreads();
    for (int o = 128; o > 0; o >>= 1) {
        if (t < o) shm[t] = fminf(shm[t], shm[t + o]);
        __syncthreads();
    }
    const float s = shm[0];
    __syncthreads();

    double acc = 0.0;
    const float* h = g_c4 + (size_t)n * 16384;
    for (int k = t; k < 16384; k += 256)
        acc += (double)h[k] * (double)w5[k];
    if (t < 32)
        acc += (double)s * (double)w5[16384 + t];

    __shared__ double shd[256];
    shd[t] = acc;
    __syncthreads();
    for (int o = 128; o > 0; o >>= 1) {
        if (t < o) shd[t] += shd[t + o];
        __syncthreads();
    }
    if (t == 0) out[n] = (float)shd[0];
}

// ---------------------------------------------------------------------------
// Launch chain. Inputs: x, w1, w2, g2, b2, w3, g3, b3, w4, g4, b4, w5
// ---------------------------------------------------------------------------
extern "C" void kernel_launch(void* const* d_in, const int* in_sizes, int n_in,
                              void* d_out, int out_size)
{
    (void)in_sizes; (void)n_in; (void)out_size;
    const float* x  = (const float*)d_in[0];
    const float* w1 = (const float*)d_in[1];
    const float* w2 = (const float*)d_in[2];
    const float* g2 = (const float*)d_in[3];
    const float* b2 = (const float*)d_in[4];
    const float* w3 = (const float*)d_in[5];
    const float* g3 = (const float*)d_in[6];
    const float* b3 = (const float*)d_in[7];
    const float* w4 = (const float*)d_in[8];
    const float* g4 = (const float*)d_in[9];
    const float* b4 = (const float*)d_in[10];
    const float* w5 = (const float*)d_in[11];
    float* out = (float*)d_out;

    float *h1, *c2, *c3, *c3p, *c4, *c4p;
    unsigned short *h1q, *c2q, *c3q;
    signed char *w2h, *w2l, *w3h, *w3l, *w4h, *w4l;
    cudaGetSymbolAddress((void**)&h1,  g_h1);
    cudaGetSymbolAddress((void**)&h1q, g_h1q);
    cudaGetSymbolAddress((void**)&c2,  g_c2);
    cudaGetSymbolAddress((void**)&c2q, g_c2q);
    cudaGetSymbolAddress((void**)&c3,  g_c3);
    cudaGetSymbolAddress((void**)&c3p, g_c3p);
    cudaGetSymbolAddress((void**)&c3q, g_c3q);
    cudaGetSymbolAddress((void**)&c4,  g_c4);
    cudaGetSymbolAddress((void**)&c4p, g_c4p);
    cudaGetSymbolAddress((void**)&w2h, g_w2h);
    cudaGetSymbolAddress((void**)&w2l, g_w2l);
    cudaGetSymbolAddress((void**)&w3h, g_w3h);
    cudaGetSymbolAddress((void**)&w3l, g_w3l);
    cudaGetSymbolAddress((void**)&w4h, g_w4h);
    cudaGetSymbolAddress((void**)&w4l, g_w4l);

    cudaFuncSetAttribute(convimma_kernel,
                         cudaFuncAttributeMaxDynamicSharedMemorySize, CI_SMEM);

    // amax init + fused weight amax/quant
    zeroamax_kernel<<<1, 32>>>();
    wamax3_kernel<<<dim3(256, 3), 256>>>((const float4*)w2, (const float4*)w3,
                                         (const float4*)w4);
    wquant3_kernel<<<dim3(4096, 3), 256>>>(w2, w3, w4,
                                           w2h, w2l, w3h, w3l, w4h, w4l);

    // L1 + padded quantize (h1: 16,32,32 -> 18,34,34; IWp2=17)
    conv1_kernel<<<dim3(16, 32, 2), 512>>>(x, w1);
    quantA_pad_kernel<<<dim3(3, 18, 2048), 256>>>(h1, (unsigned*)h1q,
        16, 32, 32, 18, 34, 17, 0);

    // L2: M=65536, N=128 (2 n-tiles), K=4096
    convimma_kernel<<<dim3(512, 2, 1), 256, CI_SMEM>>>(h1q, w2h, w2l, c2,
        64, 128, 8, 16, 16, 18, 34, 34, 4096, 0, 0, 1);
    bn_stats_kernel<<<128, 256>>>(c2, g2, b2, 128, 2048, 2);
    quantBN_pad_kernel<<<dim3(1, 10, 4096), 256>>>(c2, (unsigned*)c2q,
        127, 8, 16, 16, 10, 18, 9, 2);

    // L3: M=8192, N=256 (4 n-tiles), K=8192, split-K=2; fused reduce+stats
    convimma_kernel<<<dim3(64, 4, 2), 256, CI_SMEM>>>(c2q, w3h, w3l, c3p,
        128, 256, 4, 8, 8, 10, 18, 18, 4096, 2097152, 2, 3);
    bnstats_red_kernel<<<256, 256>>>(c3p, c3, g3, b3, 256, 256, 2, 2097152, 4);
    quantBN_pad_kernel<<<dim3(1, 6, 8192), 256>>>(c3, (unsigned*)c3q,
        255, 4, 8, 8, 6, 10, 5, 4);

    // L4: M=1024, N=512 (8 n-tiles), K=16384, split-K=8; fused reduce+stats
    convimma_kernel<<<dim3(8, 8, 8), 256, CI_SMEM>>>(c3q, w4h, w4l, c4p,
        256, 512, 2, 4, 4, 6, 10, 10, 2048, 524288, 4, 5);
    bnstats_red_kernel<<<512, 256>>>(c4p, c4, g4, b4, 512, 32, 8, 524288, -1);
    bn_lrelu_kernel<<<131072 / 256, 256>>>((float4*)c4, 512, 8, 131072);

    // minibatch discrimination + final
    pairwise_kernel<<<dim3(32, 4), 256>>>();
    final_kernel<<<32, 256>>>(w5, out);
}